// round 1
// baseline (speedup 1.0000x reference)
#include <cuda_runtime.h>

#define N_ENT 50000
#define DIM   128
#define BATCH 1024
#define NEDGE 800000
#define BN_EPS 1e-5f

// ---------------- static device scratch (no allocations allowed) ----------------
__device__ float g_bufA[N_ENT * DIM];   // GEMM outputs (T1 / T2)
__device__ float g_bufB[N_ENT * DIM];   // SpMM accumulators (bias-initialized)
__device__ float g_final[N_ENT * DIM];  // final_emb
__device__ float g_wmat[BATCH * DIM];   // R_emb[batch_rel] @ W
__device__ float g_vm[BATCH * DIM];     // bn1(bn0(x) * W_mat)
__device__ int   g_cnt[N_ENT];
__device__ int   g_rowptr[N_ENT + 1];
__device__ int   g_cur[N_ENT];
__device__ int   g_bsum[256];
__device__ int2  g_pedge[NEDGE];        // (col, val-as-int) permuted to CSR order

// ---------------- CSR build ----------------
__global__ void k_zero_cnt() {
    int gid = blockIdx.x * blockDim.x + threadIdx.x;
    if (gid < N_ENT) g_cnt[gid] = 0;
}

__global__ void k_hist(const int* __restrict__ rows) {
    int gid = blockIdx.x * blockDim.x + threadIdx.x;
    if (gid < NEDGE) atomicAdd(&g_cnt[rows[gid]], 1);
}

__global__ void k_scan1() {
    __shared__ int sh[256];
    int tid = threadIdx.x;
    int gid = blockIdx.x * 256 + tid;
    int v = (gid < N_ENT) ? g_cnt[gid] : 0;
    sh[tid] = v;
    __syncthreads();
    #pragma unroll
    for (int off = 1; off < 256; off <<= 1) {
        int t = 0;
        if (tid >= off) t = sh[tid - off];
        __syncthreads();
        sh[tid] += t;
        __syncthreads();
    }
    if (gid < N_ENT) g_rowptr[gid] = sh[tid] - v;   // block-local exclusive
    if (tid == 255) g_bsum[blockIdx.x] = sh[255];   // block total
}

__global__ void k_scan2(int nblk) {
    __shared__ int sh[256];
    int tid = threadIdx.x;
    int v = (tid < nblk) ? g_bsum[tid] : 0;
    sh[tid] = v;
    __syncthreads();
    #pragma unroll
    for (int off = 1; off < 256; off <<= 1) {
        int t = 0;
        if (tid >= off) t = sh[tid - off];
        __syncthreads();
        sh[tid] += t;
        __syncthreads();
    }
    g_bsum[tid] = sh[tid] - v;  // exclusive
}

__global__ void k_scan3() {
    int gid = blockIdx.x * blockDim.x + threadIdx.x;
    if (gid < N_ENT) {
        int v = g_rowptr[gid] + g_bsum[gid >> 8];
        g_rowptr[gid] = v;
        g_cur[gid] = v;
    }
    if (gid == 0) g_rowptr[N_ENT] = NEDGE;
}

__global__ void k_scatter(const int* __restrict__ rows, const int* __restrict__ cols,
                          const float* __restrict__ vals) {
    int gid = blockIdx.x * blockDim.x + threadIdx.x;
    if (gid < NEDGE) {
        int r = rows[gid];
        int pos = atomicAdd(&g_cur[r], 1);
        g_pedge[pos] = make_int2(cols[gid], __float_as_int(vals[gid]));
    }
}

// ---------------- GEMM: out[nrows,128] = (gather/relu X)[nrows,128] @ W[128,128] ----------------
// Block: 64 rows, 256 threads. W (64KB) + X-tile (32KB) in dynamic smem.
// Thread (rg=tid/32, cl=tid&31) computes rows rg*8..rg*8+7, cols cl*4..cl*4+3.
__global__ void k_gemm64(const float* __restrict__ X, const float* __restrict__ W,
                         const int* __restrict__ idx, float* __restrict__ out,
                         int nrows, int relu_in) {
    extern __shared__ float sh[];
    float4* Ws4 = (float4*)sh;                 // 4096 float4
    float4* Xs4 = (float4*)(sh + DIM * DIM);   // 2048 float4
    int tid = threadIdx.x;
    int base = blockIdx.x * 64;

    const float4* W4 = (const float4*)W;
    for (int l = tid; l < 4096; l += 256) Ws4[l] = W4[l];

    const float4* X4 = (const float4*)X;
    for (int l = tid; l < 2048; l += 256) {
        int r = l >> 5, kq = l & 31;
        int gr = base + r;
        float4 v = make_float4(0.f, 0.f, 0.f, 0.f);
        if (gr < nrows) {
            int sr = idx ? idx[gr] : gr;
            v = X4[(size_t)sr * 32 + kq];
            if (relu_in) {
                v.x = fmaxf(v.x, 0.f); v.y = fmaxf(v.y, 0.f);
                v.z = fmaxf(v.z, 0.f); v.w = fmaxf(v.w, 0.f);
            }
        }
        Xs4[l] = v;
    }
    __syncthreads();

    int cl = tid & 31, rg = tid >> 5;
    float4 acc[8];
    #pragma unroll
    for (int i = 0; i < 8; i++) acc[i] = make_float4(0.f, 0.f, 0.f, 0.f);

    #pragma unroll 2
    for (int k4 = 0; k4 < 32; k4++) {
        float4 w0 = Ws4[(k4 * 4 + 0) * 32 + cl];
        float4 w1 = Ws4[(k4 * 4 + 1) * 32 + cl];
        float4 w2 = Ws4[(k4 * 4 + 2) * 32 + cl];
        float4 w3 = Ws4[(k4 * 4 + 3) * 32 + cl];
        #pragma unroll
        for (int i = 0; i < 8; i++) {
            float4 x = Xs4[(rg * 8 + i) * 32 + k4];
            acc[i].x += x.x * w0.x + x.y * w1.x + x.z * w2.x + x.w * w3.x;
            acc[i].y += x.x * w0.y + x.y * w1.y + x.z * w2.y + x.w * w3.y;
            acc[i].z += x.x * w0.z + x.y * w1.z + x.z * w2.z + x.w * w3.z;
            acc[i].w += x.x * w0.w + x.y * w1.w + x.z * w2.w + x.w * w3.w;
        }
    }

    float4* O4 = (float4*)out;
    #pragma unroll
    for (int i = 0; i < 8; i++) {
        int gr = base + rg * 8 + i;
        if (gr < nrows) O4[(size_t)gr * 32 + cl] = acc[i];
    }
}

// ---------------- CSR SpMM: dst[r,:] = bias + sum_e vals[e]*src[cols[e],:]  (warp per row) ----------------
__global__ void k_spmm(const float* __restrict__ src, const float* __restrict__ bias,
                       float* __restrict__ dst) {
    int w = (blockIdx.x * blockDim.x + threadIdx.x) >> 5;
    int lane = threadIdx.x & 31;
    if (w >= N_ENT) return;
    int s = g_rowptr[w], e = g_rowptr[w + 1];
    const float4* s4 = (const float4*)src;
    float4 acc = ((const float4*)bias)[lane];
    for (int j = s; j < e; j++) {
        int2 pe = g_pedge[j];
        float v = __int_as_float(pe.y);
        float4 x = s4[(size_t)pe.x * 32 + lane];
        acc.x += v * x.x; acc.y += v * x.y; acc.z += v * x.z; acc.w += v * x.w;
    }
    ((float4*)dst)[(size_t)w * 32 + lane] = acc;
}

// ---------------- final_emb = E_emb[init_ind] + relu(bufB) ----------------
__global__ void k_final(const float* __restrict__ E, const int* __restrict__ idx) {
    int gid = blockIdx.x * blockDim.x + threadIdx.x;
    if (gid >= N_ENT * 32) return;
    int i = gid >> 5, q = gid & 31;
    float4 e4 = ((const float4*)E)[(size_t)idx[i] * 32 + q];
    float4 h = ((const float4*)g_bufB)[gid];
    e4.x += fmaxf(h.x, 0.f); e4.y += fmaxf(h.y, 0.f);
    e4.z += fmaxf(h.z, 0.f); e4.w += fmaxf(h.w, 0.f);
    ((float4*)g_final)[gid] = e4;
}

// ---------------- vm = bn1(bn0(final[batch_head]) * W_mat) ----------------
__global__ void k_vm(const int* __restrict__ bh,
                     const float* __restrict__ g0, const float* __restrict__ b0,
                     const float* __restrict__ g1, const float* __restrict__ b1) {
    int gid = blockIdx.x * blockDim.x + threadIdx.x;
    if (gid >= BATCH * 32) return;
    int b = gid >> 5, q = gid & 31;
    float s = rsqrtf(1.0f + BN_EPS);
    float4 G0 = ((const float4*)g0)[q], B0 = ((const float4*)b0)[q];
    float4 G1 = ((const float4*)g1)[q], B1 = ((const float4*)b1)[q];
    float4 x = ((const float4*)g_final)[(size_t)bh[b] * 32 + q];
    float4 wm = ((const float4*)g_wmat)[gid];
    float4 r;
    r.x = ((x.x * (G0.x * s) + B0.x) * wm.x) * (G1.x * s) + B1.x;
    r.y = ((x.y * (G0.y * s) + B0.y) * wm.y) * (G1.y * s) + B1.y;
    r.z = ((x.z * (G0.z * s) + B0.z) * wm.z) * (G1.z * s) + B1.z;
    r.w = ((x.w * (G0.w * s) + B0.w) * wm.w) * (G1.w * s) + B1.w;
    ((float4*)g_vm)[gid] = r;
}

// ---------------- big GEMM: out[b,n] = sigmoid(vm[b,:] . final[n,:]) ----------------
// 64x64 tile, 256 threads, 4x4 per thread, K=128 fully smem-resident,
// k-major float4 loads with XOR swizzle on the 16B column group.
__device__ __forceinline__ float sigmoidf(float x) {
    return 1.0f / (1.0f + __expf(-x));
}

__global__ void k_biggemm(float* __restrict__ out) {
    extern __shared__ float sh[];
    float4* As4 = (float4*)sh;          // 2048 float4 (64 rows x 32 kq)
    float4* Bs4 = (float4*)sh + 2048;   // 2048 float4
    int tid = threadIdx.x;
    int bbase = blockIdx.y * 64, nbase = blockIdx.x * 64;

    const float4* A4 = (const float4*)g_vm;
    const float4* B4 = (const float4*)g_final;
    for (int l = tid; l < 2048; l += 256) {
        int r = l >> 5, kq = l & 31;
        float4 v = A4[(size_t)(bbase + r) * 32 + kq];
        As4[r * 32 + (kq ^ ((r >> 2) & 7))] = v;
    }
    for (int l = tid; l < 2048; l += 256) {
        int r = l >> 5, kq = l & 31;
        int gn = nbase + r;
        float4 v = make_float4(0.f, 0.f, 0.f, 0.f);
        if (gn < N_ENT) v = B4[(size_t)gn * 32 + kq];
        Bs4[r * 32 + (kq ^ ((r >> 2) & 7))] = v;
    }
    __syncthreads();

    int tn = tid & 15, tb = tid >> 4;
    float acc[4][4];
    #pragma unroll
    for (int i = 0; i < 4; i++)
        #pragma unroll
        for (int j = 0; j < 4; j++) acc[i][j] = 0.f;

    #pragma unroll 2
    for (int k4 = 0; k4 < 32; k4++) {
        float4 a[4], b[4];
        int ha = k4 ^ (tb & 7);
        int hb = k4 ^ (tn & 7);
        #pragma unroll
        for (int i = 0; i < 4; i++) a[i] = As4[(tb * 4 + i) * 32 + ha];
        #pragma unroll
        for (int j = 0; j < 4; j++) b[j] = Bs4[(tn * 4 + j) * 32 + hb];
        #pragma unroll
        for (int i = 0; i < 4; i++)
            #pragma unroll
            for (int j = 0; j < 4; j++)
                acc[i][j] += a[i].x * b[j].x + a[i].y * b[j].y +
                             a[i].z * b[j].z + a[i].w * b[j].w;
    }

    int n0 = nbase + tn * 4;
    if (n0 < N_ENT) {
        #pragma unroll
        for (int i = 0; i < 4; i++) {
            int gb = bbase + tb * 4 + i;
            float4 o;
            o.x = sigmoidf(acc[i][0]); o.y = sigmoidf(acc[i][1]);
            o.z = sigmoidf(acc[i][2]); o.w = sigmoidf(acc[i][3]);
            *(float4*)&out[(size_t)gb * N_ENT + n0] = o;
        }
    }
}

// ---------------- orchestration ----------------
extern "C" void kernel_launch(void* const* d_in, const int* in_sizes, int n_in,
                              void* d_out, int out_size) {
    const float* E_emb     = (const float*)d_in[0];
    const float* R_emb     = (const float*)d_in[1];
    const float* W1        = (const float*)d_in[2];
    const float* b1        = (const float*)d_in[3];
    const float* W2        = (const float*)d_in[4];
    const float* b2        = (const float*)d_in[5];
    const float* W         = (const float*)d_in[6];
    const float* adj_vals  = (const float*)d_in[7];
    const float* bn0_gamma = (const float*)d_in[8];
    const float* bn0_beta  = (const float*)d_in[9];
    const float* bn1_gamma = (const float*)d_in[10];
    const float* bn1_beta  = (const float*)d_in[11];
    const int*   batch_head = (const int*)d_in[12];
    const int*   batch_rel  = (const int*)d_in[13];
    const int*   init_ind   = (const int*)d_in[14];
    const int*   adj_rows   = (const int*)d_in[15];
    const int*   adj_cols   = (const int*)d_in[16];
    float* out = (float*)d_out;

    float *pA, *pB, *pWM;
    cudaGetSymbolAddress((void**)&pA, g_bufA);
    cudaGetSymbolAddress((void**)&pB, g_bufB);
    cudaGetSymbolAddress((void**)&pWM, g_wmat);

    const int GEMM_SMEM = (DIM * DIM + 64 * DIM) * (int)sizeof(float);  // 98304
    const int BIG_SMEM  = 2 * 64 * DIM * (int)sizeof(float);            // 65536
    cudaFuncSetAttribute(k_gemm64, cudaFuncAttributeMaxDynamicSharedMemorySize, GEMM_SMEM);
    cudaFuncSetAttribute(k_biggemm, cudaFuncAttributeMaxDynamicSharedMemorySize, BIG_SMEM);

    const int ENT_BLKS  = (N_ENT + 255) / 256;          // 196
    const int EDGE_BLKS = (NEDGE + 255) / 256;          // 3125
    const int ROWW_BLKS = (N_ENT * 32 + 255) / 256;     // 6250

    // CSR build (adjacency is an input; rebuilt deterministically each launch)
    k_zero_cnt<<<ENT_BLKS, 256>>>();
    k_hist<<<EDGE_BLKS, 256>>>(adj_rows);
    k_scan1<<<ENT_BLKS, 256>>>();
    k_scan2<<<1, 256>>>(ENT_BLKS);
    k_scan3<<<ENT_BLKS, 256>>>();
    k_scatter<<<EDGE_BLKS, 256>>>(adj_rows, adj_cols, adj_vals);

    // Layer 1: T1 = E_emb[init_ind] @ W1 ; bufB = b1 + A @ T1
    k_gemm64<<<(N_ENT + 63) / 64, 256, GEMM_SMEM>>>(E_emb, W1, init_ind, pA, N_ENT, 0);
    k_spmm<<<ROWW_BLKS, 256>>>(pA, b1, pB);
    // Layer 2: T2 = relu(bufB) @ W2 ; bufB = b2 + A @ T2
    k_gemm64<<<(N_ENT + 63) / 64, 256, GEMM_SMEM>>>(pB, W2, nullptr, pA, N_ENT, 1);
    k_spmm<<<ROWW_BLKS, 256>>>(pA, b2, pB);
    // final_emb = E_emb[init_ind] + relu(bufB)
    k_final<<<ROWW_BLKS, 256>>>(E_emb, init_ind);

    // W_mat = R_emb[batch_rel] @ W
    k_gemm64<<<(BATCH + 63) / 64, 256, GEMM_SMEM>>>(R_emb, W, batch_rel, pWM, BATCH, 0);
    // vm = bn1(bn0(final[batch_head]) * W_mat)
    k_vm<<<(BATCH * 32 + 255) / 256, 256>>>(batch_head, bn0_gamma, bn0_beta, bn1_gamma, bn1_beta);

    // out = sigmoid(vm @ final^T)
    dim3 grid((N_ENT + 63) / 64, BATCH / 64);
    k_biggemm<<<grid, 256, BIG_SMEM>>>(out);
}

// round 3
// speedup vs baseline: 1.3764x; 1.3764x over previous
#include <cuda_runtime.h>
#include <cuda_bf16.h>
#include <cstdint>

#define N_ENT 50000
#define DIM   128
#define BATCH 1024
#define NEDGE 800000
#define BN_EPS 1e-5f

#define N_TILES 391                 // ceil(50000/128)
#define N_PAD   (N_TILES * 128)     // 50048

// ---------------- static device scratch (no allocations allowed) ----------------
__device__ float g_bufA[N_ENT * DIM];   // GEMM outputs (T1 / T2)
__device__ float g_bufB[N_ENT * DIM];   // SpMM accumulators (bias-initialized)
__device__ float g_final[N_ENT * DIM];  // final_emb
__device__ float g_wmat[BATCH * DIM];   // R_emb[batch_rel] @ W
__device__ float g_vm[BATCH * DIM];     // bn1(bn0(x) * W_mat)
__device__ int   g_cnt[N_ENT];
__device__ int   g_rowptr[N_ENT + 1];
__device__ int   g_cur[N_ENT];
__device__ int   g_bsum[256];
__device__ int2  g_pedge[NEDGE];        // (col, val-as-int) permuted to CSR order

// bf16 hi/lo splits for tensor-core big GEMM
__device__ __align__(16) __nv_bfloat16 g_finalH[N_PAD * DIM];
__device__ __align__(16) __nv_bfloat16 g_finalL[N_PAD * DIM];
__device__ __align__(16) __nv_bfloat16 g_vmH[BATCH * DIM];
__device__ __align__(16) __nv_bfloat16 g_vmL[BATCH * DIM];

// ---------------- CSR build ----------------
__global__ void k_zero_cnt() {
    int gid = blockIdx.x * blockDim.x + threadIdx.x;
    if (gid < N_ENT) g_cnt[gid] = 0;
}

__global__ void k_hist(const int* __restrict__ rows) {
    int gid = blockIdx.x * blockDim.x + threadIdx.x;
    if (gid < NEDGE) atomicAdd(&g_cnt[rows[gid]], 1);
}

__global__ void k_scan1() {
    __shared__ int sh[256];
    int tid = threadIdx.x;
    int gid = blockIdx.x * 256 + tid;
    int v = (gid < N_ENT) ? g_cnt[gid] : 0;
    sh[tid] = v;
    __syncthreads();
    #pragma unroll
    for (int off = 1; off < 256; off <<= 1) {
        int t = 0;
        if (tid >= off) t = sh[tid - off];
        __syncthreads();
        sh[tid] += t;
        __syncthreads();
    }
    if (gid < N_ENT) g_rowptr[gid] = sh[tid] - v;
    if (tid == 255) g_bsum[blockIdx.x] = sh[255];
}

__global__ void k_scan2(int nblk) {
    __shared__ int sh[256];
    int tid = threadIdx.x;
    int v = (tid < nblk) ? g_bsum[tid] : 0;
    sh[tid] = v;
    __syncthreads();
    #pragma unroll
    for (int off = 1; off < 256; off <<= 1) {
        int t = 0;
        if (tid >= off) t = sh[tid - off];
        __syncthreads();
        sh[tid] += t;
        __syncthreads();
    }
    g_bsum[tid] = sh[tid] - v;
}

__global__ void k_scan3() {
    int gid = blockIdx.x * blockDim.x + threadIdx.x;
    if (gid < N_ENT) {
        int v = g_rowptr[gid] + g_bsum[gid >> 8];
        g_rowptr[gid] = v;
        g_cur[gid] = v;
    }
    if (gid == 0) g_rowptr[N_ENT] = NEDGE;
}

__global__ void k_scatter(const int* __restrict__ rows, const int* __restrict__ cols,
                          const float* __restrict__ vals) {
    int gid = blockIdx.x * blockDim.x + threadIdx.x;
    if (gid < NEDGE) {
        int r = rows[gid];
        int pos = atomicAdd(&g_cur[r], 1);
        g_pedge[pos] = make_int2(cols[gid], __float_as_int(vals[gid]));
    }
}

// ---------------- fp32 GEMM: out[nrows,128] = (gather/relu X)[nrows,128] @ W[128,128] --------
__global__ void k_gemm64(const float* __restrict__ X, const float* __restrict__ W,
                         const int* __restrict__ idx, float* __restrict__ out,
                         int nrows, int relu_in) {
    extern __shared__ float sh[];
    float4* Ws4 = (float4*)sh;                 // 4096 float4
    float4* Xs4 = (float4*)(sh + DIM * DIM);   // 2048 float4
    int tid = threadIdx.x;
    int base = blockIdx.x * 64;

    const float4* W4 = (const float4*)W;
    for (int l = tid; l < 4096; l += 256) Ws4[l] = W4[l];

    const float4* X4 = (const float4*)X;
    for (int l = tid; l < 2048; l += 256) {
        int r = l >> 5, kq = l & 31;
        int gr = base + r;
        float4 v = make_float4(0.f, 0.f, 0.f, 0.f);
        if (gr < nrows) {
            int sr = idx ? idx[gr] : gr;
            v = X4[(size_t)sr * 32 + kq];
            if (relu_in) {
                v.x = fmaxf(v.x, 0.f); v.y = fmaxf(v.y, 0.f);
                v.z = fmaxf(v.z, 0.f); v.w = fmaxf(v.w, 0.f);
            }
        }
        Xs4[l] = v;
    }
    __syncthreads();

    int cl = tid & 31, rg = tid >> 5;
    float4 acc[8];
    #pragma unroll
    for (int i = 0; i < 8; i++) acc[i] = make_float4(0.f, 0.f, 0.f, 0.f);

    #pragma unroll 2
    for (int k4 = 0; k4 < 32; k4++) {
        float4 w0 = Ws4[(k4 * 4 + 0) * 32 + cl];
        float4 w1 = Ws4[(k4 * 4 + 1) * 32 + cl];
        float4 w2 = Ws4[(k4 * 4 + 2) * 32 + cl];
        float4 w3 = Ws4[(k4 * 4 + 3) * 32 + cl];
        #pragma unroll
        for (int i = 0; i < 8; i++) {
            float4 x = Xs4[(rg * 8 + i) * 32 + k4];
            acc[i].x += x.x * w0.x + x.y * w1.x + x.z * w2.x + x.w * w3.x;
            acc[i].y += x.x * w0.y + x.y * w1.y + x.z * w2.y + x.w * w3.y;
            acc[i].z += x.x * w0.z + x.y * w1.z + x.z * w2.z + x.w * w3.z;
            acc[i].w += x.x * w0.w + x.y * w1.w + x.z * w2.w + x.w * w3.w;
        }
    }

    float4* O4 = (float4*)out;
    #pragma unroll
    for (int i = 0; i < 8; i++) {
        int gr = base + rg * 8 + i;
        if (gr < nrows) O4[(size_t)gr * 32 + cl] = acc[i];
    }
}

// ---------------- CSR SpMM: dst[r,:] = bias + sum_e vals[e]*src[cols[e],:] (warp per row) ----
__global__ void k_spmm(const float* __restrict__ src, const float* __restrict__ bias,
                       float* __restrict__ dst) {
    int w = (blockIdx.x * blockDim.x + threadIdx.x) >> 5;
    int lane = threadIdx.x & 31;
    if (w >= N_ENT) return;
    int s = g_rowptr[w], e = g_rowptr[w + 1];
    const float4* s4 = (const float4*)src;
    float4 acc = ((const float4*)bias)[lane];
    for (int j = s; j < e; j++) {
        int2 pe = g_pedge[j];
        float v = __int_as_float(pe.y);
        float4 x = s4[(size_t)pe.x * 32 + lane];
        acc.x += v * x.x; acc.y += v * x.y; acc.z += v * x.z; acc.w += v * x.w;
    }
    ((float4*)dst)[(size_t)w * 32 + lane] = acc;
}

// ---------------- final_emb = E_emb[init_ind] + relu(bufB) ----------------
__global__ void k_final(const float* __restrict__ E, const int* __restrict__ idx) {
    int gid = blockIdx.x * blockDim.x + threadIdx.x;
    if (gid >= N_ENT * 32) return;
    int i = gid >> 5, q = gid & 31;
    float4 e4 = ((const float4*)E)[(size_t)idx[i] * 32 + q];
    float4 h = ((const float4*)g_bufB)[gid];
    e4.x += fmaxf(h.x, 0.f); e4.y += fmaxf(h.y, 0.f);
    e4.z += fmaxf(h.z, 0.f); e4.w += fmaxf(h.w, 0.f);
    ((float4*)g_final)[gid] = e4;
}

// ---------------- vm = bn1(bn0(final[batch_head]) * W_mat) ----------------
__global__ void k_vm(const int* __restrict__ bh,
                     const float* __restrict__ g0, const float* __restrict__ b0,
                     const float* __restrict__ g1, const float* __restrict__ b1) {
    int gid = blockIdx.x * blockDim.x + threadIdx.x;
    if (gid >= BATCH * 32) return;
    int b = gid >> 5, q = gid & 31;
    float s = rsqrtf(1.0f + BN_EPS);
    float4 G0 = ((const float4*)g0)[q], B0 = ((const float4*)b0)[q];
    float4 G1 = ((const float4*)g1)[q], B1 = ((const float4*)b1)[q];
    float4 x = ((const float4*)g_final)[(size_t)bh[b] * 32 + q];
    float4 wm = ((const float4*)g_wmat)[gid];
    float4 r;
    r.x = ((x.x * (G0.x * s) + B0.x) * wm.x) * (G1.x * s) + B1.x;
    r.y = ((x.y * (G0.y * s) + B0.y) * wm.y) * (G1.y * s) + B1.y;
    r.z = ((x.z * (G0.z * s) + B0.z) * wm.z) * (G1.z * s) + B1.z;
    r.w = ((x.w * (G0.w * s) + B0.w) * wm.w) * (G1.w * s) + B1.w;
    ((float4*)g_vm)[gid] = r;
}

// ---------------- bf16 hi/lo split conversions ----------------
__device__ __forceinline__ uint32_t pack_bf2(float a, float b) {
    __nv_bfloat162 t = __floats2bfloat162_rn(a, b);
    return *(uint32_t*)&t;
}
__device__ __forceinline__ void split4(float4 v, uint2& hi, uint2& lo) {
    float hx = __bfloat162float(__float2bfloat16_rn(v.x));
    float hy = __bfloat162float(__float2bfloat16_rn(v.y));
    float hz = __bfloat162float(__float2bfloat16_rn(v.z));
    float hw = __bfloat162float(__float2bfloat16_rn(v.w));
    hi.x = pack_bf2(hx, hy);
    hi.y = pack_bf2(hz, hw);
    lo.x = pack_bf2(v.x - hx, v.y - hy);
    lo.y = pack_bf2(v.z - hz, v.w - hw);
}

__global__ void k_cvt_final() {
    int gid = blockIdx.x * blockDim.x + threadIdx.x;   // one per 4 elems
    if (gid >= N_PAD * 32) return;
    int row = gid >> 5;
    uint2 hi = make_uint2(0u, 0u), lo = make_uint2(0u, 0u);
    if (row < N_ENT) {
        float4 v = ((const float4*)g_final)[gid];
        split4(v, hi, lo);
    }
    ((uint2*)g_finalH)[gid] = hi;
    ((uint2*)g_finalL)[gid] = lo;
}

__global__ void k_cvt_vm() {
    int gid = blockIdx.x * blockDim.x + threadIdx.x;
    if (gid >= BATCH * 32) return;
    float4 v = ((const float4*)g_vm)[gid];
    uint2 hi, lo;
    split4(v, hi, lo);
    ((uint2*)g_vmH)[gid] = hi;
    ((uint2*)g_vmL)[gid] = lo;
}

// ---------------- big GEMM via mma.sync (HMMA bf16): out = sigmoid(vm @ final^T) ------------
// One CTA per 128x128 output tile; 256 threads = 8 warps (2 m x 4 n), warp tile 64x32.
// 3xBF16 emulation: D = AH*BH + AH*BL + AL*BH, accumulated in f32.
// SMEM: 4 tiles [128 rows x 128 bf16] each 32 KB, k-major, chunk-XOR swizzled.
#define TB_AH 0
#define TB_AL 32768
#define TB_BH 65536
#define TB_BL 98304
#define TB_SMEM 131072

__device__ __forceinline__ uint32_t smem_u32(const void* p) {
    uint32_t a;
    asm("{ .reg .u64 t; cvta.to.shared.u64 t, %1; cvt.u32.u64 %0, t; }" : "=r"(a) : "l"(p));
    return a;
}

__device__ __forceinline__ void ldsm_x4(uint32_t addr, uint32_t* r) {
    asm volatile("ldmatrix.sync.aligned.m8n8.x4.shared.b16 {%0,%1,%2,%3}, [%4];"
                 : "=r"(r[0]), "=r"(r[1]), "=r"(r[2]), "=r"(r[3]) : "r"(addr));
}

__device__ __forceinline__ void mma_bf16(float* d, const uint32_t* a, uint32_t b0, uint32_t b1) {
    asm volatile(
        "mma.sync.aligned.m16n8k16.row.col.f32.bf16.bf16.f32 "
        "{%0,%1,%2,%3}, {%4,%5,%6,%7}, {%8,%9}, {%0,%1,%2,%3};"
        : "+f"(d[0]), "+f"(d[1]), "+f"(d[2]), "+f"(d[3])
        : "r"(a[0]), "r"(a[1]), "r"(a[2]), "r"(a[3]), "r"(b0), "r"(b1));
}

__device__ __forceinline__ float sigmoidf(float x) {
    return 1.0f / (1.0f + __expf(-x));
}

__global__ void __launch_bounds__(256, 1) k_mma_biggemm(float* __restrict__ out) {
    extern __shared__ char sm[];
    int tid = threadIdx.x;
    int nbase = blockIdx.x * 128;     // entity tile
    int bbase = blockIdx.y * 128;     // batch tile

    // ---- load 4 tiles, swizzled: phys_chunk = chunk ^ (row & 7), rows are 256B (16 chunks)
    const uint4* Ah = (const uint4*)g_vmH;
    const uint4* Al = (const uint4*)g_vmL;
    const uint4* Bh = (const uint4*)g_finalH;
    const uint4* Bl = (const uint4*)g_finalL;
    #pragma unroll
    for (int l = tid; l < 2048; l += 256) {
        int r = l >> 4, c = l & 15;
        int off = r * 256 + (c ^ (r & 7)) * 16;
        size_t ia = (size_t)(bbase + r) * 16 + c;
        size_t ib = (size_t)(nbase + r) * 16 + c;
        *(uint4*)(sm + TB_AH + off) = Ah[ia];
        *(uint4*)(sm + TB_AL + off) = Al[ia];
        *(uint4*)(sm + TB_BH + off) = Bh[ib];
        *(uint4*)(sm + TB_BL + off) = Bl[ib];
    }
    __syncthreads();

    uint32_t smb = smem_u32(sm);
    int wid = tid >> 5, lane = tid & 31;
    int wm = wid >> 2, wn = wid & 3;          // 2 x 4 warp grid
    int lrow = lane & 15;                     // ldmatrix row within 16-row tile
    int lkh = lane >> 4;                      // ldmatrix k-half (0/1) -> +16B

    float acc[4][4][4];                       // [m-tile][n-tile][frag]
    #pragma unroll
    for (int i = 0; i < 4; i++)
        #pragma unroll
        for (int j = 0; j < 4; j++)
            #pragma unroll
            for (int f = 0; f < 4; f++) acc[i][j][f] = 0.f;

    #pragma unroll
    for (int term = 0; term < 3; term++) {
        uint32_t aBase = smb + (term == 2 ? TB_AL : TB_AH);
        uint32_t bBase = smb + (term == 1 ? TB_BL : TB_BH);
        #pragma unroll
        for (int ks = 0; ks < 8; ks++) {
            int kchunk = ks * 2 + lkh;                     // logical 16B chunk (0..15)
            uint32_t a[4][4];
            #pragma unroll
            for (int i = 0; i < 4; i++) {
                int row = wm * 64 + i * 16 + lrow;
                uint32_t addr = aBase + row * 256 + ((kchunk ^ (row & 7)) << 4);
                ldsm_x4(addr, a[i]);
            }
            uint32_t b[2][4];
            #pragma unroll
            for (int j2 = 0; j2 < 2; j2++) {
                int row = wn * 32 + j2 * 16 + lrow;
                uint32_t addr = bBase + row * 256 + ((kchunk ^ (row & 7)) << 4);
                ldsm_x4(addr, b[j2]);
            }
            #pragma unroll
            for (int i = 0; i < 4; i++)
                #pragma unroll
                for (int j = 0; j < 4; j++)
                    mma_bf16(acc[i][j], a[i], b[j >> 1][j & 1], b[j >> 1][2 + (j & 1)]);
        }
    }

    // ---- epilogue: sigmoid + store (pairs along n; N_ENT even so pairs never straddle)
    int q = lane >> 2, p = lane & 3;
    #pragma unroll
    for (int i = 0; i < 4; i++) {
        int brow = bbase + wm * 64 + i * 16 + q;
        #pragma unroll
        for (int j = 0; j < 4; j++) {
            int n = nbase + wn * 32 + j * 8 + p * 2;
            if (n < N_ENT) {
                float2 o0, o1;
                o0.x = sigmoidf(acc[i][j][0]); o0.y = sigmoidf(acc[i][j][1]);
                o1.x = sigmoidf(acc[i][j][2]); o1.y = sigmoidf(acc[i][j][3]);
                *(float2*)(out + (size_t)brow * N_ENT + n) = o0;
                *(float2*)(out + (size_t)(brow + 8) * N_ENT + n) = o1;
            }
        }
    }
}

// ---------------- orchestration ----------------
extern "C" void kernel_launch(void* const* d_in, const int* in_sizes, int n_in,
                              void* d_out, int out_size) {
    const float* E_emb     = (const float*)d_in[0];
    const float* R_emb     = (const float*)d_in[1];
    const float* W1        = (const float*)d_in[2];
    const float* b1        = (const float*)d_in[3];
    const float* W2        = (const float*)d_in[4];
    const float* b2        = (const float*)d_in[5];
    const float* W         = (const float*)d_in[6];
    const float* adj_vals  = (const float*)d_in[7];
    const float* bn0_gamma = (const float*)d_in[8];
    const float* bn0_beta  = (const float*)d_in[9];
    const float* bn1_gamma = (const float*)d_in[10];
    const float* bn1_beta  = (const float*)d_in[11];
    const int*   batch_head = (const int*)d_in[12];
    const int*   batch_rel  = (const int*)d_in[13];
    const int*   init_ind   = (const int*)d_in[14];
    const int*   adj_rows   = (const int*)d_in[15];
    const int*   adj_cols   = (const int*)d_in[16];
    float* out = (float*)d_out;

    float *pA, *pB, *pWM;
    cudaGetSymbolAddress((void**)&pA, g_bufA);
    cudaGetSymbolAddress((void**)&pB, g_bufB);
    cudaGetSymbolAddress((void**)&pWM, g_wmat);

    const int GEMM_SMEM = (DIM * DIM + 64 * DIM) * (int)sizeof(float);  // 98304
    cudaFuncSetAttribute(k_gemm64, cudaFuncAttributeMaxDynamicSharedMemorySize, GEMM_SMEM);
    cudaFuncSetAttribute(k_mma_biggemm, cudaFuncAttributeMaxDynamicSharedMemorySize, TB_SMEM);

    const int ENT_BLKS  = (N_ENT + 255) / 256;
    const int EDGE_BLKS = (NEDGE + 255) / 256;
    const int ROWW_BLKS = (N_ENT * 32 + 255) / 256;

    // CSR build
    k_zero_cnt<<<ENT_BLKS, 256>>>();
    k_hist<<<EDGE_BLKS, 256>>>(adj_rows);
    k_scan1<<<ENT_BLKS, 256>>>();
    k_scan2<<<1, 256>>>(ENT_BLKS);
    k_scan3<<<ENT_BLKS, 256>>>();
    k_scatter<<<EDGE_BLKS, 256>>>(adj_rows, adj_cols, adj_vals);

    // GNN layers
    k_gemm64<<<(N_ENT + 63) / 64, 256, GEMM_SMEM>>>(E_emb, W1, init_ind, pA, N_ENT, 0);
    k_spmm<<<ROWW_BLKS, 256>>>(pA, b1, pB);
    k_gemm64<<<(N_ENT + 63) / 64, 256, GEMM_SMEM>>>(pB, W2, nullptr, pA, N_ENT, 1);
    k_spmm<<<ROWW_BLKS, 256>>>(pA, b2, pB);
    k_final<<<ROWW_BLKS, 256>>>(E_emb, init_ind);

    // scoring head inputs
    k_gemm64<<<(BATCH + 63) / 64, 256, GEMM_SMEM>>>(R_emb, W, batch_rel, pWM, BATCH, 0);
    k_vm<<<(BATCH * 32 + 255) / 256, 256>>>(batch_head, bn0_gamma, bn0_beta, bn1_gamma, bn1_beta);

    // bf16 splits
    k_cvt_final<<<(N_PAD * 32 + 255) / 256, 256>>>();
    k_cvt_vm<<<(BATCH * 32 + 255) / 256, 256>>>();

    // tensor-core scoring GEMM + sigmoid
    dim3 grid(N_TILES, BATCH / 128);
    k_mma_biggemm<<<grid, 256, TB_SMEM>>>(out);
}

// round 5
// speedup vs baseline: 1.6058x; 1.1667x over previous
#include <cuda_runtime.h>
#include <cuda_bf16.h>
#include <cstdint>

#define N_ENT 50000
#define DIM   128
#define BATCH 1024
#define NEDGE 800000
#define BN_EPS 1e-5f

#define N_TILES 391                 // ceil(50000/128)
#define N_PAD   (N_TILES * 128)     // 50048
#define TILES_TOTAL (8 * N_TILES)   // 3128

// ---------------- static device scratch (no allocations allowed) ----------------
__device__ float g_bufA[N_ENT * DIM];   // layer GEMM outputs
__device__ float g_bufB[N_ENT * DIM];   // SpMM accumulators
__device__ float g_final[N_ENT * DIM];  // final_emb (f32, for k_vm gather)
__device__ float g_wmat[BATCH * DIM];   // R_emb[batch_rel] @ W
__device__ int   g_cnt[N_ENT];
__device__ int   g_rowptr[N_ENT + 1];
__device__ int   g_cur[N_ENT];
__device__ int   g_bsum[256];
__device__ int2  g_pedge[NEDGE];

// bf16 hi/lo splits
__device__ __align__(16) __nv_bfloat16 g_finalH[N_PAD * DIM];
__device__ __align__(16) __nv_bfloat16 g_finalL[N_PAD * DIM];
__device__ __align__(16) __nv_bfloat16 g_vmH[BATCH * DIM];
__device__ __align__(16) __nv_bfloat16 g_vmL[BATCH * DIM];
// transposed+split weights: [n][k] k-major
__device__ __align__(16) __nv_bfloat16 g_WT1H[DIM * DIM];
__device__ __align__(16) __nv_bfloat16 g_WT1L[DIM * DIM];
__device__ __align__(16) __nv_bfloat16 g_WT2H[DIM * DIM];
__device__ __align__(16) __nv_bfloat16 g_WT2L[DIM * DIM];
__device__ __align__(16) __nv_bfloat16 g_WTWH[DIM * DIM];
__device__ __align__(16) __nv_bfloat16 g_WTWL[DIM * DIM];

// ---------------- helpers ----------------
__device__ __forceinline__ uint32_t smem_u32(const void* p) {
    uint32_t a;
    asm("{ .reg .u64 t; cvta.to.shared.u64 t, %1; cvt.u32.u64 %0, t; }" : "=r"(a) : "l"(p));
    return a;
}
__device__ __forceinline__ void ldsm_x4(uint32_t addr, uint32_t* r) {
    asm volatile("ldmatrix.sync.aligned.m8n8.x4.shared.b16 {%0,%1,%2,%3}, [%4];"
                 : "=r"(r[0]), "=r"(r[1]), "=r"(r[2]), "=r"(r[3]) : "r"(addr));
}
__device__ __forceinline__ void mma_bf16(float* d, const uint32_t* a, uint32_t b0, uint32_t b1) {
    asm volatile(
        "mma.sync.aligned.m16n8k16.row.col.f32.bf16.bf16.f32 "
        "{%0,%1,%2,%3}, {%4,%5,%6,%7}, {%8,%9}, {%0,%1,%2,%3};"
        : "+f"(d[0]), "+f"(d[1]), "+f"(d[2]), "+f"(d[3])
        : "r"(a[0]), "r"(a[1]), "r"(a[2]), "r"(a[3]), "r"(b0), "r"(b1));
}
__device__ __forceinline__ void cp16(uint32_t saddr, const void* g) {
    asm volatile("cp.async.cg.shared.global [%0], [%1], 16;" :: "r"(saddr), "l"(g) : "memory");
}
__device__ __forceinline__ float sigmoidf(float x) {
    return 1.0f / (1.0f + __expf(-x));
}
__device__ __forceinline__ uint32_t pack_bf2(float a, float b) {
    __nv_bfloat162 t = __floats2bfloat162_rn(a, b);
    return *(uint32_t*)&t;
}
__device__ __forceinline__ void split4(float4 v, uint2& hi, uint2& lo) {
    float hx = __bfloat162float(__float2bfloat16_rn(v.x));
    float hy = __bfloat162float(__float2bfloat16_rn(v.y));
    float hz = __bfloat162float(__float2bfloat16_rn(v.z));
    float hw = __bfloat162float(__float2bfloat16_rn(v.w));
    hi.x = pack_bf2(hx, hy);  hi.y = pack_bf2(hz, hw);
    lo.x = pack_bf2(v.x - hx, v.y - hy);
    lo.y = pack_bf2(v.z - hz, v.w - hw);
}

// ---------------- CSR build ----------------
__global__ void k_zero_cnt() {
    int gid = blockIdx.x * blockDim.x + threadIdx.x;
    if (gid < N_ENT) g_cnt[gid] = 0;
}
__global__ void k_hist(const int* __restrict__ rows) {
    int gid = blockIdx.x * blockDim.x + threadIdx.x;
    if (gid < NEDGE) atomicAdd(&g_cnt[rows[gid]], 1);
}
__global__ void k_scan1() {
    __shared__ int sh[256];
    int tid = threadIdx.x;
    int gid = blockIdx.x * 256 + tid;
    int v = (gid < N_ENT) ? g_cnt[gid] : 0;
    sh[tid] = v;
    __syncthreads();
    #pragma unroll
    for (int off = 1; off < 256; off <<= 1) {
        int t = 0;
        if (tid >= off) t = sh[tid - off];
        __syncthreads();
        sh[tid] += t;
        __syncthreads();
    }
    if (gid < N_ENT) g_rowptr[gid] = sh[tid] - v;
    if (tid == 255) g_bsum[blockIdx.x] = sh[255];
}
__global__ void k_scan2(int nblk) {
    __shared__ int sh[256];
    int tid = threadIdx.x;
    int v = (tid < nblk) ? g_bsum[tid] : 0;
    sh[tid] = v;
    __syncthreads();
    #pragma unroll
    for (int off = 1; off < 256; off <<= 1) {
        int t = 0;
        if (tid >= off) t = sh[tid - off];
        __syncthreads();
        sh[tid] += t;
        __syncthreads();
    }
    g_bsum[tid] = sh[tid] - v;
}
__global__ void k_scan3() {
    int gid = blockIdx.x * blockDim.x + threadIdx.x;
    if (gid < N_ENT) {
        int v = g_rowptr[gid] + g_bsum[gid >> 8];
        g_rowptr[gid] = v;
        g_cur[gid] = v;
    }
    if (gid == 0) g_rowptr[N_ENT] = NEDGE;
}
__global__ void k_scatter(const int* __restrict__ rows, const int* __restrict__ cols,
                          const float* __restrict__ vals) {
    int gid = blockIdx.x * blockDim.x + threadIdx.x;
    if (gid < NEDGE) {
        int r = rows[gid];
        int pos = atomicAdd(&g_cur[r], 1);
        g_pedge[pos] = make_int2(cols[gid], __float_as_int(vals[gid]));
    }
}

// ---------------- weight transpose + split: WT_H/L[n*128+k] = split(W[k*128+n]) ----------------
__global__ void k_split_w(const float* __restrict__ W1, const float* __restrict__ W2,
                          const float* __restrict__ W) {
    int gid = blockIdx.x * blockDim.x + threadIdx.x;
    if (gid >= 3 * DIM * DIM) return;
    int m = gid >> 14, rem = gid & 16383, k = rem >> 7, n = rem & 127;
    const float* src = (m == 0) ? W1 : (m == 1) ? W2 : W;
    __nv_bfloat16* dh = (m == 0) ? g_WT1H : (m == 1) ? g_WT2H : g_WTWH;
    __nv_bfloat16* dl = (m == 0) ? g_WT1L : (m == 1) ? g_WT2L : g_WTWL;
    float v = src[k * DIM + n];
    __nv_bfloat16 h = __float2bfloat16_rn(v);
    dh[n * DIM + k] = h;
    dl[n * DIM + k] = __float2bfloat16_rn(v - __bfloat162float(h));
}

// ---------------- HMMA layer GEMM: out[r,0:128] = (gather/relu X)[r,:] @ W ----------------
// 128-row CTA, 256 thr / 8 warps (2m x 4n), warp tile 64x32, 3-term bf16 emulation.
// SMEM: XH 32K | XL 32K | WH 32K | WL 32K = 128 KB.
#define LG_XH 0
#define LG_XL 32768
#define LG_WH 65536
#define LG_WL 98304
#define LG_SMEM 131072

__global__ void __launch_bounds__(256, 1) k_hgemm(
        const float* __restrict__ X,
        const __nv_bfloat16* __restrict__ WT_H, const __nv_bfloat16* __restrict__ WT_L,
        const int* __restrict__ idx, float* __restrict__ out, int nrows, int relu_in) {
    extern __shared__ char sm[];
    int tid = threadIdx.x;
    int rbase = blockIdx.x * 128;

    // W tiles (k-major [n][k], swizzled)
    const uint4* wh = (const uint4*)WT_H;
    const uint4* wl = (const uint4*)WT_L;
    #pragma unroll
    for (int l = tid; l < 2048; l += 256) {
        int r = l >> 4, c = l & 15;
        int off = r * 256 + ((c ^ (r & 7)) << 4);
        *(uint4*)(sm + LG_WH + off) = wh[l];
        *(uint4*)(sm + LG_WL + off) = wl[l];
    }
    // X tile: gather + relu + split
    #pragma unroll
    for (int l = tid; l < 2048; l += 256) {
        int r = l >> 4, c = l & 15;     // c = 8-float chunk
        int gr = rbase + r;
        float4 v0 = make_float4(0.f, 0.f, 0.f, 0.f), v1 = v0;
        if (gr < nrows) {
            int sr = idx ? idx[gr] : gr;
            const float4* xp = (const float4*)X + (size_t)sr * 32 + c * 2;
            v0 = xp[0]; v1 = xp[1];
            if (relu_in) {
                v0.x = fmaxf(v0.x, 0.f); v0.y = fmaxf(v0.y, 0.f);
                v0.z = fmaxf(v0.z, 0.f); v0.w = fmaxf(v0.w, 0.f);
                v1.x = fmaxf(v1.x, 0.f); v1.y = fmaxf(v1.y, 0.f);
                v1.z = fmaxf(v1.z, 0.f); v1.w = fmaxf(v1.w, 0.f);
            }
        }
        uint2 h0, l0, h1, l1;
        split4(v0, h0, l0); split4(v1, h1, l1);
        int off = r * 256 + ((c ^ (r & 7)) << 4);
        *(uint4*)(sm + LG_XH + off) = make_uint4(h0.x, h0.y, h1.x, h1.y);
        *(uint4*)(sm + LG_XL + off) = make_uint4(l0.x, l0.y, l1.x, l1.y);
    }
    __syncthreads();

    uint32_t smb = smem_u32(sm);
    int wid = tid >> 5, lane = tid & 31;
    int wm = wid >> 2, wn = wid & 3;
    int lrow = lane & 15, lkh = lane >> 4;

    float acc[4][4][4];
    #pragma unroll
    for (int i = 0; i < 4; i++)
        #pragma unroll
        for (int j = 0; j < 4; j++)
            #pragma unroll
            for (int f = 0; f < 4; f++) acc[i][j][f] = 0.f;

    #pragma unroll
    for (int term = 0; term < 3; term++) {
        uint32_t aBase = smb + (term == 2 ? LG_XL : LG_XH);
        uint32_t bBase = smb + (term == 1 ? LG_WL : LG_WH);
        #pragma unroll
        for (int ks = 0; ks < 8; ks++) {
            int kchunk = ks * 2 + lkh;
            uint32_t a[4][4];
            #pragma unroll
            for (int i = 0; i < 4; i++) {
                int row = wm * 64 + i * 16 + lrow;
                ldsm_x4(aBase + row * 256 + ((kchunk ^ (row & 7)) << 4), a[i]);
            }
            uint32_t b[2][4];
            #pragma unroll
            for (int j2 = 0; j2 < 2; j2++) {
                int row = wn * 32 + j2 * 16 + lrow;
                ldsm_x4(bBase + row * 256 + ((kchunk ^ (row & 7)) << 4), b[j2]);
            }
            #pragma unroll
            for (int i = 0; i < 4; i++)
                #pragma unroll
                for (int j = 0; j < 4; j++)
                    mma_bf16(acc[i][j], a[i], b[j >> 1][j & 1], b[j >> 1][2 + (j & 1)]);
        }
    }

    int q = lane >> 2, p = lane & 3;
    #pragma unroll
    for (int i = 0; i < 4; i++) {
        int r0 = rbase + wm * 64 + i * 16 + q;
        #pragma unroll
        for (int j = 0; j < 4; j++) {
            int n = wn * 32 + j * 8 + p * 2;
            if (r0 < nrows)
                *(float2*)(out + (size_t)r0 * DIM + n) = make_float2(acc[i][j][0], acc[i][j][1]);
            if (r0 + 8 < nrows)
                *(float2*)(out + (size_t)(r0 + 8) * DIM + n) = make_float2(acc[i][j][2], acc[i][j][3]);
        }
    }
}

// ---------------- CSR SpMM (warp per row) ----------------
__global__ void k_spmm(const float* __restrict__ src, const float* __restrict__ bias,
                       float* __restrict__ dst) {
    int w = (blockIdx.x * blockDim.x + threadIdx.x) >> 5;
    int lane = threadIdx.x & 31;
    if (w >= N_ENT) return;
    int s = g_rowptr[w], e = g_rowptr[w + 1];
    const float4* s4 = (const float4*)src;
    float4 acc = ((const float4*)bias)[lane];
    for (int j = s; j < e; j++) {
        int2 pe = g_pedge[j];
        float v = __int_as_float(pe.y);
        float4 x = s4[(size_t)pe.x * 32 + lane];
        acc.x += v * x.x; acc.y += v * x.y; acc.z += v * x.z; acc.w += v * x.w;
    }
    ((float4*)dst)[(size_t)w * 32 + lane] = acc;
}

// ---------------- fused: final_emb = E[init_ind] + relu(bufB); + bf16 hi/lo split ----------
__global__ void k_final_cvt(const float* __restrict__ E, const int* __restrict__ idx) {
    int gid = blockIdx.x * blockDim.x + threadIdx.x;
    if (gid >= N_PAD * 32) return;
    int row = gid >> 5, qq = gid & 31;
    uint2 hi = make_uint2(0u, 0u), lo = make_uint2(0u, 0u);
    if (row < N_ENT) {
        float4 e4 = ((const float4*)E)[(size_t)idx[row] * 32 + qq];
        float4 h = ((const float4*)g_bufB)[gid];
        e4.x += fmaxf(h.x, 0.f); e4.y += fmaxf(h.y, 0.f);
        e4.z += fmaxf(h.z, 0.f); e4.w += fmaxf(h.w, 0.f);
        ((float4*)g_final)[gid] = e4;
        split4(e4, hi, lo);
    }
    ((uint2*)g_finalH)[gid] = hi;
    ((uint2*)g_finalL)[gid] = lo;
}

// ---------------- fused: vm = bn1(bn0(final[bh]) * wmat); + split ----------------
__global__ void k_vm_split(const int* __restrict__ bh,
                           const float* __restrict__ g0, const float* __restrict__ b0,
                           const float* __restrict__ g1, const float* __restrict__ b1) {
    int gid = blockIdx.x * blockDim.x + threadIdx.x;
    if (gid >= BATCH * 32) return;
    int b = gid >> 5, qq = gid & 31;
    float s = rsqrtf(1.0f + BN_EPS);
    float4 G0 = ((const float4*)g0)[qq], B0 = ((const float4*)b0)[qq];
    float4 G1 = ((const float4*)g1)[qq], B1 = ((const float4*)b1)[qq];
    float4 x = ((const float4*)g_final)[(size_t)bh[b] * 32 + qq];
    float4 wm = ((const float4*)g_wmat)[gid];
    float4 r;
    r.x = ((x.x * (G0.x * s) + B0.x) * wm.x) * (G1.x * s) + B1.x;
    r.y = ((x.y * (G0.y * s) + B0.y) * wm.y) * (G1.y * s) + B1.y;
    r.z = ((x.z * (G0.z * s) + B0.z) * wm.z) * (G1.z * s) + B1.z;
    r.w = ((x.w * (G0.w * s) + B0.w) * wm.w) * (G1.w * s) + B1.w;
    uint2 hi, lo;
    split4(r, hi, lo);
    ((uint2*)g_vmH)[gid] = hi;
    ((uint2*)g_vmL)[gid] = lo;
}

// ---------------- persistent double-buffered big GEMM: out = sigmoid(vm @ final^T) --------
// SMEM: AH 32K | AL 32K | B0(H+L) 64K | B1(H+L) 64K = 192 KB.
#define PG_AH 0
#define PG_AL 32768
#define PG_B0 65536
#define PG_B1 131072
#define PG_SMEM 196608

__global__ void __launch_bounds__(256, 1) k_biggemm_persist(float* __restrict__ out) {
    extern __shared__ char sm[];
    uint32_t smb = smem_u32(sm);
    int tid = threadIdx.x;
    int cta = blockIdx.x;

    // balanced contiguous chunks: 3128 = 20*22 + 128*21
    int start, cnt;
    if (cta < 20) { start = cta * 22; cnt = 22; }
    else          { start = 440 + (cta - 20) * 21; cnt = 21; }
    int end = start + cnt;

    const uint4* Ah = (const uint4*)g_vmH;
    const uint4* Al = (const uint4*)g_vmL;
    const uint4* Bh = (const uint4*)g_finalH;
    const uint4* Bl = (const uint4*)g_finalL;

    int wid = tid >> 5, lane = tid & 31;
    int wm = wid >> 2, wn = wid & 3;
    int lrow = lane & 15, lkh = lane >> 4;
    int q = lane >> 2, p = lane & 3;

    int cur_b = -1, buf = 0, loaded = 0;

    for (int t = start; t < end; t++) {
        int b = t / N_TILES, n = t - b * N_TILES;
        __syncthreads();   // all readers of the target buffer are done

        if (!loaded) {
            if (b != cur_b) {
                int bbase = b * 128;
                #pragma unroll
                for (int l = tid; l < 2048; l += 256) {
                    int r = l >> 4, c = l & 15;
                    uint32_t off = r * 256 + ((c ^ (r & 7)) << 4);
                    cp16(smb + PG_AH + off, Ah + (size_t)(bbase + r) * 16 + c);
                    cp16(smb + PG_AL + off, Al + (size_t)(bbase + r) * 16 + c);
                }
                cur_b = b;
            }
            int nbase = n * 128;
            uint32_t sb = smb + (buf ? PG_B1 : PG_B0);
            #pragma unroll
            for (int l = tid; l < 2048; l += 256) {
                int r = l >> 4, c = l & 15;
                uint32_t off = r * 256 + ((c ^ (r & 7)) << 4);
                cp16(sb + off,         Bh + (size_t)(nbase + r) * 16 + c);
                cp16(sb + 32768 + off, Bl + (size_t)(nbase + r) * 16 + c);
            }
            asm volatile("cp.async.commit_group;" ::: "memory");
        }

        // prefetch next tile's B into the other buffer (same A)
        int pf = 0;
        if (t + 1 < end) {
            int b2 = (t + 1) / N_TILES, n2 = (t + 1) - b2 * N_TILES;
            if (b2 == cur_b) {
                int nbase2 = n2 * 128;
                uint32_t sb2 = smb + (buf ? PG_B0 : PG_B1);
                #pragma unroll
                for (int l = tid; l < 2048; l += 256) {
                    int r = l >> 4, c = l & 15;
                    uint32_t off = r * 256 + ((c ^ (r & 7)) << 4);
                    cp16(sb2 + off,         Bh + (size_t)(nbase2 + r) * 16 + c);
                    cp16(sb2 + 32768 + off, Bl + (size_t)(nbase2 + r) * 16 + c);
                }
                asm volatile("cp.async.commit_group;" ::: "memory");
                pf = 1;
            }
        }
        if (pf) asm volatile("cp.async.wait_group 1;" ::: "memory");
        else    asm volatile("cp.async.wait_group 0;" ::: "memory");
        __syncthreads();

        // ---- compute tile (b, n)
        uint32_t sb = smb + (buf ? PG_B1 : PG_B0);
        float acc[4][4][4];
        #pragma unroll
        for (int i = 0; i < 4; i++)
            #pragma unroll
            for (int j = 0; j < 4; j++)
                #pragma unroll
                for (int f = 0; f < 4; f++) acc[i][j][f] = 0.f;

        #pragma unroll
        for (int term = 0; term < 3; term++) {
            uint32_t aBase = smb + (term == 2 ? PG_AL : PG_AH);
            uint32_t bBase = sb + (term == 1 ? 32768 : 0);
            #pragma unroll
            for (int ks = 0; ks < 8; ks++) {
                int kchunk = ks * 2 + lkh;
                uint32_t a[4][4];
                #pragma unroll
                for (int i = 0; i < 4; i++) {
                    int row = wm * 64 + i * 16 + lrow;
                    ldsm_x4(aBase + row * 256 + ((kchunk ^ (row & 7)) << 4), a[i]);
                }
                uint32_t bfr[2][4];
                #pragma unroll
                for (int j2 = 0; j2 < 2; j2++) {
                    int row = wn * 32 + j2 * 16 + lrow;
                    ldsm_x4(bBase + row * 256 + ((kchunk ^ (row & 7)) << 4), bfr[j2]);
                }
                #pragma unroll
                for (int i = 0; i < 4; i++)
                    #pragma unroll
                    for (int j = 0; j < 4; j++)
                        mma_bf16(acc[i][j], a[i], bfr[j >> 1][j & 1], bfr[j >> 1][2 + (j & 1)]);
            }
        }

        // epilogue: sigmoid + store
        int bbase = b * 128, nbase = n * 128;
        #pragma unroll
        for (int i = 0; i < 4; i++) {
            int brow = bbase + wm * 64 + i * 16 + q;
            #pragma unroll
            for (int j = 0; j < 4; j++) {
                int nn = nbase + wn * 32 + j * 8 + p * 2;
                if (nn < N_ENT) {
                    float2 o0, o1;
                    o0.x = sigmoidf(acc[i][j][0]); o0.y = sigmoidf(acc[i][j][1]);
                    o1.x = sigmoidf(acc[i][j][2]); o1.y = sigmoidf(acc[i][j][3]);
                    *(float2*)(out + (size_t)brow * N_ENT + nn) = o0;
                    *(float2*)(out + (size_t)(brow + 8) * N_ENT + nn) = o1;
                }
            }
        }

        loaded = pf;
        buf ^= 1;
    }
}

// ---------------- orchestration ----------------
extern "C" void kernel_launch(void* const* d_in, const int* in_sizes, int n_in,
                              void* d_out, int out_size) {
    const float* E_emb     = (const float*)d_in[0];
    const float* R_emb     = (const float*)d_in[1];
    const float* W1        = (const float*)d_in[2];
    const float* b1        = (const float*)d_in[3];
    const float* W2        = (const float*)d_in[4];
    const float* b2        = (const float*)d_in[5];
    const float* W         = (const float*)d_in[6];
    const float* adj_vals  = (const float*)d_in[7];
    const float* bn0_gamma = (const float*)d_in[8];
    const float* bn0_beta  = (const float*)d_in[9];
    const float* bn1_gamma = (const float*)d_in[10];
    const float* bn1_beta  = (const float*)d_in[11];
    const int*   batch_head = (const int*)d_in[12];
    const int*   batch_rel  = (const int*)d_in[13];
    const int*   init_ind   = (const int*)d_in[14];
    const int*   adj_rows   = (const int*)d_in[15];
    const int*   adj_cols   = (const int*)d_in[16];
    float* out = (float*)d_out;

    float *pA, *pB, *pWM;
    cudaGetSymbolAddress((void**)&pA, g_bufA);
    cudaGetSymbolAddress((void**)&pB, g_bufB);
    cudaGetSymbolAddress((void**)&pWM, g_wmat);
    __nv_bfloat16 *w1h, *w1l, *w2h, *w2l, *wwh, *wwl;
    cudaGetSymbolAddress((void**)&w1h, g_WT1H);
    cudaGetSymbolAddress((void**)&w1l, g_WT1L);
    cudaGetSymbolAddress((void**)&w2h, g_WT2H);
    cudaGetSymbolAddress((void**)&w2l, g_WT2L);
    cudaGetSymbolAddress((void**)&wwh, g_WTWH);
    cudaGetSymbolAddress((void**)&wwl, g_WTWL);

    cudaFuncSetAttribute(k_hgemm, cudaFuncAttributeMaxDynamicSharedMemorySize, LG_SMEM);
    cudaFuncSetAttribute(k_biggemm_persist, cudaFuncAttributeMaxDynamicSharedMemorySize, PG_SMEM);

    const int ENT_BLKS  = (N_ENT + 255) / 256;
    const int EDGE_BLKS = (NEDGE + 255) / 256;
    const int ROWW_BLKS = (N_ENT * 32 + 255) / 256;

    // CSR build
    k_zero_cnt<<<ENT_BLKS, 256>>>();
    k_hist<<<EDGE_BLKS, 256>>>(adj_rows);
    k_scan1<<<ENT_BLKS, 256>>>();
    k_scan2<<<1, 256>>>(ENT_BLKS);
    k_scan3<<<ENT_BLKS, 256>>>();
    k_scatter<<<EDGE_BLKS, 256>>>(adj_rows, adj_cols, adj_vals);

    // weight splits (independent of CSR)
    k_split_w<<<(3 * DIM * DIM + 255) / 256, 256>>>(W1, W2, W);

    // GNN layers (HMMA)
    k_hgemm<<<N_TILES, 256, LG_SMEM>>>(E_emb, w1h, w1l, init_ind, pA, N_ENT, 0);
    k_spmm<<<ROWW_BLKS, 256>>>(pA, b1, pB);
    k_hgemm<<<N_TILES, 256, LG_SMEM>>>(pB, w2h, w2l, nullptr, pA, N_ENT, 1);
    k_spmm<<<ROWW_BLKS, 256>>>(pA, b2, pB);
    k_final_cvt<<<(N_PAD * 32 + 255) / 256, 256>>>(E_emb, init_ind);

    // scoring head
    k_hgemm<<<(BATCH + 127) / 128, 256, LG_SMEM>>>(R_emb, wwh, wwl, batch_rel, pWM, BATCH, 0);
    k_vm_split<<<(BATCH * 32 + 255) / 256, 256>>>(batch_head, bn0_gamma, bn0_beta, bn1_gamma, bn1_beta);

    // persistent tensor-core scoring GEMM + sigmoid
    k_biggemm_persist<<<148, 256, PG_SMEM>>>(out);
}

// round 8
// speedup vs baseline: 1.8882x; 1.1759x over previous
#include <cuda_runtime.h>
#include <cuda_bf16.h>
#include <cstdint>

#define N_ENT 50000
#define DIM   128
#define BATCH 1024
#define NEDGE 800000
#define BN_EPS 1e-5f

#define N_TILES 391                 // ceil(50000/128)
#define N_PAD   (N_TILES * 128)     // 50048
#define READY_BIT 0x40000000

// ---------------- static device scratch (no allocations allowed) ----------------
__device__ float g_bufA[N_ENT * DIM];   // layer GEMM outputs
__device__ float g_final[N_ENT * DIM];  // final_emb (f32, for vm gather)
__device__ float g_wmat[BATCH * DIM];   // R_emb[batch_rel] @ W
__device__ int   g_cnt[N_ENT];
__device__ int   g_rowptr[N_ENT + 1];
__device__ int   g_cur[N_ENT];
__device__ int   g_bsum[256];
__device__ int2  g_pedge[NEDGE];

// bf16 hi/lo splits (padded rows >= N_ENT stay zero from static init; never written)
__device__ __align__(16) __nv_bfloat16 g_h1H[N_PAD * DIM];      // relu(layer1) split
__device__ __align__(16) __nv_bfloat16 g_h1L[N_PAD * DIM];
__device__ __align__(16) __nv_bfloat16 g_finalH[N_PAD * DIM];
__device__ __align__(16) __nv_bfloat16 g_finalL[N_PAD * DIM];
__device__ __align__(16) __nv_bfloat16 g_vmH[BATCH * DIM];
__device__ __align__(16) __nv_bfloat16 g_vmL[BATCH * DIM];
// transposed+split weights: [n][k] k-major
__device__ __align__(16) __nv_bfloat16 g_WT1H[DIM * DIM];
__device__ __align__(16) __nv_bfloat16 g_WT1L[DIM * DIM];
__device__ __align__(16) __nv_bfloat16 g_WT2H[DIM * DIM];
__device__ __align__(16) __nv_bfloat16 g_WT2L[DIM * DIM];
__device__ __align__(16) __nv_bfloat16 g_WTWH[DIM * DIM];
__device__ __align__(16) __nv_bfloat16 g_WTWL[DIM * DIM];

// ---------------- helpers ----------------
__device__ __forceinline__ uint32_t smem_u32(const void* p) {
    uint32_t a;
    asm("{ .reg .u64 t; cvta.to.shared.u64 t, %1; cvt.u32.u64 %0, t; }" : "=r"(a) : "l"(p));
    return a;
}
__device__ __forceinline__ void ldsm_x4(uint32_t addr, uint32_t* r) {
    asm volatile("ldmatrix.sync.aligned.m8n8.x4.shared.b16 {%0,%1,%2,%3}, [%4];"
                 : "=r"(r[0]), "=r"(r[1]), "=r"(r[2]), "=r"(r[3]) : "r"(addr));
}
__device__ __forceinline__ void mma_bf16(float* d, const uint32_t* a, uint32_t b0, uint32_t b1) {
    asm volatile(
        "mma.sync.aligned.m16n8k16.row.col.f32.bf16.bf16.f32 "
        "{%0,%1,%2,%3}, {%4,%5,%6,%7}, {%8,%9}, {%0,%1,%2,%3};"
        : "+f"(d[0]), "+f"(d[1]), "+f"(d[2]), "+f"(d[3])
        : "r"(a[0]), "r"(a[1]), "r"(a[2]), "r"(a[3]), "r"(b0), "r"(b1));
}
__device__ __forceinline__ void cp16(uint32_t saddr, const void* g) {
    asm volatile("cp.async.cg.shared.global [%0], [%1], 16;" :: "r"(saddr), "l"(g) : "memory");
}
__device__ __forceinline__ float sigmoidf(float x) {
    return 1.0f / (1.0f + __expf(-x));
}
__device__ __forceinline__ uint32_t pack_bf2(float a, float b) {
    __nv_bfloat162 t = __floats2bfloat162_rn(a, b);
    return *(uint32_t*)&t;
}
__device__ __forceinline__ void split4(float4 v, uint2& hi, uint2& lo) {
    float hx = __bfloat162float(__float2bfloat16_rn(v.x));
    float hy = __bfloat162float(__float2bfloat16_rn(v.y));
    float hz = __bfloat162float(__float2bfloat16_rn(v.z));
    float hw = __bfloat162float(__float2bfloat16_rn(v.w));
    hi.x = pack_bf2(hx, hy);  hi.y = pack_bf2(hz, hw);
    lo.x = pack_bf2(v.x - hx, v.y - hy);
    lo.y = pack_bf2(v.z - hz, v.w - hw);
}

// 3-term emulated bf16 MMA over a 128x128x128 tile held in 4 swizzled SMEM tiles.
// Fragments loaded once per k-step, reused across terms: AH*BH + AH*BL + AL*BH.
__device__ __forceinline__ void mma_tile_3term(
        uint32_t aHb, uint32_t aLb, uint32_t bHb, uint32_t bLb,
        int wm, int wn, int lrow, int lkh, float acc[4][4][4]) {
    #pragma unroll
    for (int ks = 0; ks < 8; ks++) {
        int kchunk = ks * 2 + lkh;
        uint32_t aH[4][4], aL[4][4], bH[2][4], bL[2][4];
        #pragma unroll
        for (int i = 0; i < 4; i++) {
            int row = wm * 64 + i * 16 + lrow;
            uint32_t o = row * 256 + ((kchunk ^ (row & 7)) << 4);
            ldsm_x4(aHb + o, aH[i]);
            ldsm_x4(aLb + o, aL[i]);
        }
        #pragma unroll
        for (int j2 = 0; j2 < 2; j2++) {
            int row = wn * 32 + j2 * 16 + lrow;
            uint32_t o = row * 256 + ((kchunk ^ (row & 7)) << 4);
            ldsm_x4(bHb + o, bH[j2]);
            ldsm_x4(bLb + o, bL[j2]);
        }
        #pragma unroll
        for (int i = 0; i < 4; i++)
            #pragma unroll
            for (int j = 0; j < 4; j++) {
                uint32_t h0 = bH[j >> 1][j & 1], h1 = bH[j >> 1][2 + (j & 1)];
                uint32_t l0 = bL[j >> 1][j & 1], l1 = bL[j >> 1][2 + (j & 1)];
                mma_bf16(acc[i][j], aH[i], h0, h1);
                mma_bf16(acc[i][j], aH[i], l0, l1);
                mma_bf16(acc[i][j], aL[i], h0, h1);
            }
    }
}

// ---------------- k_prep: edge histogram + weight transpose/split + g_bsum reset --------
__global__ void k_prep(const int* __restrict__ rows, int edge_blks,
                       const float* __restrict__ W1, const float* __restrict__ W2,
                       const float* __restrict__ W) {
    int tid = threadIdx.x;
    if ((int)blockIdx.x < edge_blks) {
        if (blockIdx.x == 0) g_bsum[tid] = 0;
        int gid = blockIdx.x * 256 + tid;
        if (gid < NEDGE) atomicAdd(&g_cnt[rows[gid]], 1);
    } else {
        int gid = (blockIdx.x - edge_blks) * 256 + tid;   // 0 .. 3*16384-1
        int m = gid >> 14, rem = gid & 16383, k = rem >> 7, n = rem & 127;
        const float* src = (m == 0) ? W1 : (m == 1) ? W2 : W;
        __nv_bfloat16* dh = (m == 0) ? g_WT1H : (m == 1) ? g_WT2H : g_WTWH;
        __nv_bfloat16* dl = (m == 0) ? g_WT1L : (m == 1) ? g_WT2L : g_WTWL;
        float v = src[k * DIM + n];
        __nv_bfloat16 h = __float2bfloat16_rn(v);
        dh[n * DIM + k] = h;
        dl[n * DIM + k] = __float2bfloat16_rn(v - __bfloat162float(h));
    }
}

// ---------------- single-launch scan (decoupled partials; all 196 blocks co-resident) ----
__global__ void k_scan_lb() {
    __shared__ int sh[256];
    __shared__ int red[256];
    int tid = threadIdx.x, b = blockIdx.x;
    int gid = b * 256 + tid;
    int v = (gid < N_ENT) ? g_cnt[gid] : 0;
    if (gid < N_ENT) g_cnt[gid] = 0;              // leave zeroed for next launch
    sh[tid] = v;
    __syncthreads();
    #pragma unroll
    for (int off = 1; off < 256; off <<= 1) {
        int t = 0;
        if (tid >= off) t = sh[tid - off];
        __syncthreads();
        sh[tid] += t;
        __syncthreads();
    }
    if (tid == 0) atomicExch(&g_bsum[b], sh[255] | READY_BIT);
    int myp = 0;
    if (tid < b) {
        int p;
        do { p = *(volatile int*)&g_bsum[tid]; } while (!(p & READY_BIT));
        myp = p & ~READY_BIT;
    }
    red[tid] = myp;
    __syncthreads();
    #pragma unroll
    for (int off = 128; off > 0; off >>= 1) {
        if (tid < off) red[tid] += red[tid + off];
        __syncthreads();
    }
    int prefix = red[0];
    if (gid < N_ENT) {
        int val = prefix + sh[tid] - v;
        g_rowptr[gid] = val;
        g_cur[gid] = val;
    }
    if (b == 0 && tid == 0) g_rowptr[N_ENT] = NEDGE;
}

__global__ void k_scatter(const int* __restrict__ rows, const int* __restrict__ cols,
                          const float* __restrict__ vals) {
    int gid = blockIdx.x * blockDim.x + threadIdx.x;
    if (gid < NEDGE) {
        int r = rows[gid];
        int pos = atomicAdd(&g_cur[r], 1);
        g_pedge[pos] = make_int2(cols[gid], __float_as_int(vals[gid]));
    }
}

// ---------------- HMMA GEMM, f32 gathered input (layer1 + wmat combined) ----------------
#define LG_XH 0
#define LG_XL 32768
#define LG_WH 65536
#define LG_WL 98304
#define LG_SMEM 131072

__global__ void __launch_bounds__(256, 1) k_hgemm1c(
        const float* __restrict__ E, const float* __restrict__ R,
        const int* __restrict__ init_ind, const int* __restrict__ batch_rel,
        float* __restrict__ outA, float* __restrict__ outW) {
    extern __shared__ char sm[];
    int tid = threadIdx.x;

    const float* X;
    const __nv_bfloat16 *WTH, *WTL;
    const int* idx;
    float* out;
    int nrows, rbase;
    if ((int)blockIdx.x < N_TILES) {
        X = E;  WTH = g_WT1H; WTL = g_WT1L; idx = init_ind;  out = outA; nrows = N_ENT;
        rbase = blockIdx.x * 128;
    } else {
        X = R;  WTH = g_WTWH; WTL = g_WTWL; idx = batch_rel; out = outW; nrows = BATCH;
        rbase = (blockIdx.x - N_TILES) * 128;
    }

    const uint4* wh = (const uint4*)WTH;
    const uint4* wl = (const uint4*)WTL;
    #pragma unroll
    for (int l = tid; l < 2048; l += 256) {
        int r = l >> 4, c = l & 15;
        int off = r * 256 + ((c ^ (r & 7)) << 4);
        *(uint4*)(sm + LG_WH + off) = wh[l];
        *(uint4*)(sm + LG_WL + off) = wl[l];
    }
    #pragma unroll
    for (int l = tid; l < 2048; l += 256) {
        int r = l >> 4, c = l & 15;
        int gr = rbase + r;
        float4 v0 = make_float4(0.f, 0.f, 0.f, 0.f), v1 = v0;
        if (gr < nrows) {
            const float4* xp = (const float4*)X + (size_t)idx[gr] * 32 + c * 2;
            v0 = xp[0]; v1 = xp[1];
        }
        uint2 h0, l0, h1, l1;
        split4(v0, h0, l0); split4(v1, h1, l1);
        int off = r * 256 + ((c ^ (r & 7)) << 4);
        *(uint4*)(sm + LG_XH + off) = make_uint4(h0.x, h0.y, h1.x, h1.y);
        *(uint4*)(sm + LG_XL + off) = make_uint4(l0.x, l0.y, l1.x, l1.y);
    }
    __syncthreads();

    uint32_t smb = smem_u32(sm);
    int wid = tid >> 5, lane = tid & 31;
    int wm = wid >> 2, wn = wid & 3;
    int lrow = lane & 15, lkh = lane >> 4;

    float acc[4][4][4];
    #pragma unroll
    for (int i = 0; i < 4; i++)
        #pragma unroll
        for (int j = 0; j < 4; j++)
            #pragma unroll
            for (int f = 0; f < 4; f++) acc[i][j][f] = 0.f;

    mma_tile_3term(smb + LG_XH, smb + LG_XL, smb + LG_WH, smb + LG_WL,
                   wm, wn, lrow, lkh, acc);

    int q = lane >> 2, p = lane & 3;
    #pragma unroll
    for (int i = 0; i < 4; i++) {
        int r0 = rbase + wm * 64 + i * 16 + q;
        #pragma unroll
        for (int j = 0; j < 4; j++) {
            int n = wn * 32 + j * 8 + p * 2;
            if (r0 < nrows)
                *(float2*)(out + (size_t)r0 * DIM + n) = make_float2(acc[i][j][0], acc[i][j][1]);
            if (r0 + 8 < nrows)
                *(float2*)(out + (size_t)(r0 + 8) * DIM + n) = make_float2(acc[i][j][2], acc[i][j][3]);
        }
    }
}

// ---------------- HMMA GEMM, pre-split bf16 input (layer 2) ----------------
__global__ void __launch_bounds__(256, 1) k_hgemm2b(float* __restrict__ out) {
    extern __shared__ char sm[];
    uint32_t smb = smem_u32(sm);
    int tid = threadIdx.x;
    int rbase = blockIdx.x * 128;

    const uint4* xh = (const uint4*)g_h1H + (size_t)rbase * 16;
    const uint4* xl = (const uint4*)g_h1L + (size_t)rbase * 16;
    const uint4* wh = (const uint4*)g_WT2H;
    const uint4* wl = (const uint4*)g_WT2L;
    #pragma unroll
    for (int l = tid; l < 2048; l += 256) {
        int r = l >> 4, c = l & 15;
        uint32_t off = r * 256 + ((c ^ (r & 7)) << 4);
        cp16(smb + LG_XH + off, xh + l);
        cp16(smb + LG_XL + off, xl + l);
        cp16(smb + LG_WH + off, wh + l);
        cp16(smb + LG_WL + off, wl + l);
    }
    asm volatile("cp.async.commit_group;" ::: "memory");
    asm volatile("cp.async.wait_group 0;" ::: "memory");
    __syncthreads();

    int wid = tid >> 5, lane = tid & 31;
    int wm = wid >> 2, wn = wid & 3;
    int lrow = lane & 15, lkh = lane >> 4;

    float acc[4][4][4];
    #pragma unroll
    for (int i = 0; i < 4; i++)
        #pragma unroll
        for (int j = 0; j < 4; j++)
            #pragma unroll
            for (int f = 0; f < 4; f++) acc[i][j][f] = 0.f;

    mma_tile_3term(smb + LG_XH, smb + LG_XL, smb + LG_WH, smb + LG_WL,
                   wm, wn, lrow, lkh, acc);

    int q = lane >> 2, p = lane & 3;
    #pragma unroll
    for (int i = 0; i < 4; i++) {
        int r0 = rbase + wm * 64 + i * 16 + q;
        #pragma unroll
        for (int j = 0; j < 4; j++) {
            int n = wn * 32 + j * 8 + p * 2;
            if (r0 < N_ENT)
                *(float2*)(out + (size_t)r0 * DIM + n) = make_float2(acc[i][j][0], acc[i][j][1]);
            if (r0 + 8 < N_ENT)
                *(float2*)(out + (size_t)(r0 + 8) * DIM + n) = make_float2(acc[i][j][2], acc[i][j][3]);
        }
    }
}

// ---------------- SpMM 1: h1 = split(relu(b1 + A @ src)) ----------------
__global__ void k_spmm1(const float* __restrict__ src, const float* __restrict__ bias) {
    int w = (blockIdx.x * blockDim.x + threadIdx.x) >> 5;
    int lane = threadIdx.x & 31;
    if (w >= N_ENT) return;
    int s = g_rowptr[w], e = g_rowptr[w + 1];
    const float4* s4 = (const float4*)src;
    float4 acc = ((const float4*)bias)[lane];
    for (int j = s; j < e; j++) {
        int2 pe = g_pedge[j];
        float v = __int_as_float(pe.y);
        float4 x = s4[(size_t)pe.x * 32 + lane];
        acc.x += v * x.x; acc.y += v * x.y; acc.z += v * x.z; acc.w += v * x.w;
    }
    acc.x = fmaxf(acc.x, 0.f); acc.y = fmaxf(acc.y, 0.f);
    acc.z = fmaxf(acc.z, 0.f); acc.w = fmaxf(acc.w, 0.f);
    uint2 hi, lo;
    split4(acc, hi, lo);
    ((uint2*)g_h1H)[w * 32 + lane] = hi;
    ((uint2*)g_h1L)[w * 32 + lane] = lo;
}

// ---------------- SpMM 2 fused: final = E[init] + relu(b2 + A @ src); + split ----------
__global__ void k_spmm2f(const float* __restrict__ src, const float* __restrict__ bias,
                         const float* __restrict__ E, const int* __restrict__ idx) {
    int w = (blockIdx.x * blockDim.x + threadIdx.x) >> 5;
    int lane = threadIdx.x & 31;
    if (w >= N_ENT) return;
    int s = g_rowptr[w], e = g_rowptr[w + 1];
    const float4* s4 = (const float4*)src;
    float4 acc = ((const float4*)bias)[lane];
    for (int j = s; j < e; j++) {
        int2 pe = g_pedge[j];
        float v = __int_as_float(pe.y);
        float4 x = s4[(size_t)pe.x * 32 + lane];
        acc.x += v * x.x; acc.y += v * x.y; acc.z += v * x.z; acc.w += v * x.w;
    }
    float4 e4 = ((const float4*)E)[(size_t)idx[w] * 32 + lane];
    e4.x += fmaxf(acc.x, 0.f); e4.y += fmaxf(acc.y, 0.f);
    e4.z += fmaxf(acc.z, 0.f); e4.w += fmaxf(acc.w, 0.f);
    ((float4*)g_final)[w * 32 + lane] = e4;
    uint2 hi, lo;
    split4(e4, hi, lo);
    ((uint2*)g_finalH)[w * 32 + lane] = hi;
    ((uint2*)g_finalL)[w * 32 + lane] = lo;
}

// ---------------- vm = bn1(bn0(final[bh]) * wmat); + split ----------------
__global__ void k_vm_split(const int* __restrict__ bh,
                           const float* __restrict__ g0, const float* __restrict__ b0,
                           const float* __restrict__ g1, const float* __restrict__ b1) {
    int gid = blockIdx.x * blockDim.x + threadIdx.x;
    if (gid >= BATCH * 32) return;
    int b = gid >> 5, qq = gid & 31;
    float s = rsqrtf(1.0f + BN_EPS);
    float4 G0 = ((const float4*)g0)[qq], B0 = ((const float4*)b0)[qq];
    float4 G1 = ((const float4*)g1)[qq], B1 = ((const float4*)b1)[qq];
    float4 x = ((const float4*)g_final)[(size_t)bh[b] * 32 + qq];
    float4 wm = ((const float4*)g_wmat)[gid];
    float4 r;
    r.x = ((x.x * (G0.x * s) + B0.x) * wm.x) * (G1.x * s) + B1.x;
    r.y = ((x.y * (G0.y * s) + B0.y) * wm.y) * (G1.y * s) + B1.y;
    r.z = ((x.z * (G0.z * s) + B0.z) * wm.z) * (G1.z * s) + B1.z;
    r.w = ((x.w * (G0.w * s) + B0.w) * wm.w) * (G1.w * s) + B1.w;
    uint2 hi, lo;
    split4(r, hi, lo);
    ((uint2*)g_vmH)[gid] = hi;
    ((uint2*)g_vmL)[gid] = lo;
}

// ---------------- persistent double-buffered big GEMM: out = sigmoid(vm @ final^T) --------
#define PG_AH 0
#define PG_AL 32768
#define PG_B0 65536
#define PG_B1 131072
#define PG_SMEM 196608

__global__ void __launch_bounds__(256, 1) k_biggemm_persist(float* __restrict__ out) {
    extern __shared__ char sm[];
    uint32_t smb = smem_u32(sm);
    int tid = threadIdx.x;
    int cta = blockIdx.x;

    // balanced contiguous chunks: 3128 = 20*22 + 128*21
    int start, cnt;
    if (cta < 20) { start = cta * 22; cnt = 22; }
    else          { start = 440 + (cta - 20) * 21; cnt = 21; }
    int end = start + cnt;

    const uint4* Ah = (const uint4*)g_vmH;
    const uint4* Al = (const uint4*)g_vmL;
    const uint4* Bh = (const uint4*)g_finalH;
    const uint4* Bl = (const uint4*)g_finalL;

    int wid = tid >> 5, lane = tid & 31;
    int wm = wid >> 2, wn = wid & 3;
    int lrow = lane & 15, lkh = lane >> 4;
    int q = lane >> 2, p = lane & 3;

    int cur_b = -1, buf = 0, loaded = 0;

    for (int t = start; t < end; t++) {
        int b = t / N_TILES, n = t - b * N_TILES;
        __syncthreads();

        if (!loaded) {
            if (b != cur_b) {
                int bbase = b * 128;
                #pragma unroll
                for (int l = tid; l < 2048; l += 256) {
                    int r = l >> 4, c = l & 15;
                    uint32_t off = r * 256 + ((c ^ (r & 7)) << 4);
                    cp16(smb + PG_AH + off, Ah + (size_t)(bbase + r) * 16 + c);
                    cp16(smb + PG_AL + off, Al + (size_t)(bbase + r) * 16 + c);
                }
                cur_b = b;
            }
            int nbase = n * 128;
            uint32_t sb = smb + (buf ? PG_B1 : PG_B0);
            #pragma unroll
            for (int l = tid; l < 2048; l += 256) {
                int r = l >> 4, c = l & 15;
                uint32_t off = r * 256 + ((c ^ (r & 7)) << 4);
                cp16(sb + off,         Bh + (size_t)(nbase + r) * 16 + c);
                cp16(sb + 32768 + off, Bl + (size_t)(nbase + r) * 16 + c);
            }
            asm volatile("cp.async.commit_group;" ::: "memory");
        }

        int pf = 0;
        if (t + 1 < end) {
            int b2 = (t + 1) / N_TILES, n2 = (t + 1) - b2 * N_TILES;
            if (b2 == cur_b) {
                int nbase2 = n2 * 128;
                uint32_t sb2 = smb + (buf ? PG_B0 : PG_B1);
                #pragma unroll
                for (int l = tid; l < 2048; l += 256) {
                    int r = l >> 4, c = l & 15;
                    uint32_t off = r * 256 + ((c ^ (r & 7)) << 4);
                    cp16(sb2 + off,         Bh + (size_t)(nbase2 + r) * 16 + c);
                    cp16(sb2 + 32768 + off, Bl + (size_t)(nbase2 + r) * 16 + c);
                }
                asm volatile("cp.async.commit_group;" ::: "memory");
                pf = 1;
            }
        }
        if (pf) asm volatile("cp.async.wait_group 1;" ::: "memory");
        else    asm volatile("cp.async.wait_group 0;" ::: "memory");
        __syncthreads();

        uint32_t sb = smb + (buf ? PG_B1 : PG_B0);
        float acc[4][4][4];
        #pragma unroll
        for (int i = 0; i < 4; i++)
            #pragma unroll
            for (int j = 0; j < 4; j++)
                #pragma unroll
                for (int f = 0; f < 4; f++) acc[i][j][f] = 0.f;

        mma_tile_3term(smb + PG_AH, smb + PG_AL, sb, sb + 32768,
                       wm, wn, lrow, lkh, acc);

        int bbase = b * 128, nbase = n * 128;
        #pragma unroll
        for (int i = 0; i < 4; i++) {
            int brow = bbase + wm * 64 + i * 16 + q;
            #pragma unroll
            for (int j = 0; j < 4; j++) {
                int nn = nbase + wn * 32 + j * 8 + p * 2;
                if (nn < N_ENT) {
                    float2 o0, o1;
                    o0.x = sigmoidf(acc[i][j][0]); o0.y = sigmoidf(acc[i][j][1]);
                    o1.x = sigmoidf(acc[i][j][2]); o1.y = sigmoidf(acc[i][j][3]);
                    *(float2*)(out + (size_t)brow * N_ENT + nn) = o0;
                    *(float2*)(out + (size_t)(brow + 8) * N_ENT + nn) = o1;
                }
            }
        }

        loaded = pf;
        buf ^= 1;
    }
}

// ---------------- orchestration ----------------
extern "C" void kernel_launch(void* const* d_in, const int* in_sizes, int n_in,
                              void* d_out, int out_size) {
    const float* E_emb     = (const float*)d_in[0];
    const float* R_emb     = (const float*)d_in[1];
    const float* W1        = (const float*)d_in[2];
    const float* b1        = (const float*)d_in[3];
    const float* W2        = (const float*)d_in[4];
    const float* b2        = (const float*)d_in[5];
    const float* W         = (const float*)d_in[6];
    const float* adj_vals  = (const float*)d_in[7];
    const float* bn0_gamma = (const float*)d_in[8];
    const float* bn0_beta  = (const float*)d_in[9];
    const float* bn1_gamma = (const float*)d_in[10];
    const float* bn1_beta  = (const float*)d_in[11];
    const int*   batch_head = (const int*)d_in[12];
    const int*   batch_rel  = (const int*)d_in[13];
    const int*   init_ind   = (const int*)d_in[14];
    const int*   adj_rows   = (const int*)d_in[15];
    const int*   adj_cols   = (const int*)d_in[16];
    float* out = (float*)d_out;

    float *pA, *pWM;
    cudaGetSymbolAddress((void**)&pA, g_bufA);
    cudaGetSymbolAddress((void**)&pWM, g_wmat);

    cudaFuncSetAttribute(k_hgemm1c, cudaFuncAttributeMaxDynamicSharedMemorySize, LG_SMEM);
    cudaFuncSetAttribute(k_hgemm2b, cudaFuncAttributeMaxDynamicSharedMemorySize, LG_SMEM);
    cudaFuncSetAttribute(k_biggemm_persist, cudaFuncAttributeMaxDynamicSharedMemorySize, PG_SMEM);

    const int EDGE_BLKS = (NEDGE + 255) / 256;          // 3125
    const int ENT_BLKS  = (N_ENT + 255) / 256;          // 196
    const int ROWW_BLKS = (N_ENT * 32 + 255) / 256;     // 6250

    // 1. histogram + weight splits (+ g_bsum reset)
    k_prep<<<EDGE_BLKS + 192, 256>>>(adj_rows, EDGE_BLKS, W1, W2, W);
    // 2. single-launch scan (also zeroes g_cnt for next launch)
    k_scan_lb<<<ENT_BLKS, 256>>>();
    // 3. CSR scatter
    k_scatter<<<EDGE_BLKS, 256>>>(adj_rows, adj_cols, adj_vals);
    // 4. layer-1 GEMM + wmat GEMM (combined launch)
    k_hgemm1c<<<N_TILES + BATCH / 128, 256, LG_SMEM>>>(E_emb, R_emb, init_ind, batch_rel, pA, pWM);
    // 5. SpMM1 (+relu+split)
    k_spmm1<<<ROWW_BLKS, 256>>>(pA, b1);
    // 6. layer-2 GEMM (bf16 in, f32 out)
    k_hgemm2b<<<N_TILES, 256, LG_SMEM>>>(pA);
    // 7. SpMM2 (+residual+relu+split)
    k_spmm2f<<<ROWW_BLKS, 256>>>(pA, b2, E_emb, init_ind);
    // 8. vm (+split)
    k_vm_split<<<(BATCH * 32 + 255) / 256, 256>>>(batch_head, bn0_gamma, bn0_beta, bn1_gamma, bn1_beta);
    // 9. persistent tensor-core scoring GEMM + sigmoid
    k_biggemm_persist<<<148, 256, PG_SMEM>>>(out);
}

// round 9
// speedup vs baseline: 2.2185x; 1.1749x over previous
#include <cuda_runtime.h>
#include <cuda_bf16.h>
#include <cstdint>

#define N_ENT 50000
#define DIM   128
#define BATCH 1024
#define NEDGE 800000
#define BN_EPS 1e-5f

#define N_TILES 391                 // ceil(50000/128)
#define N_PAD   (N_TILES * 128)     // 50048
#define READY_BIT 0x40000000

// ---------------- static device scratch (no allocations allowed) ----------------
__device__ float g_bufA[N_ENT * DIM];   // layer GEMM outputs
__device__ float g_final[N_ENT * DIM];  // final_emb (f32, for vm gather)
__device__ float g_wmat[BATCH * DIM];   // R_emb[batch_rel] @ W
__device__ int   g_cnt[N_ENT];
__device__ int   g_rowptr[N_ENT + 1];
__device__ int   g_cur[N_ENT];
__device__ int   g_bsum[256];
__device__ int2  g_pedge[NEDGE];

// bf16 hi/lo splits (padded rows >= N_ENT stay zero from static init; never written)
__device__ __align__(16) __nv_bfloat16 g_h1H[N_PAD * DIM];      // relu(layer1) split
__device__ __align__(16) __nv_bfloat16 g_h1L[N_PAD * DIM];
__device__ __align__(16) __nv_bfloat16 g_finalH[N_PAD * DIM];
__device__ __align__(16) __nv_bfloat16 g_finalL[N_PAD * DIM];
__device__ __align__(16) __nv_bfloat16 g_vmH[BATCH * DIM];
__device__ __align__(16) __nv_bfloat16 g_vmL[BATCH * DIM];
// transposed+split weights: [n][k] k-major
__device__ __align__(16) __nv_bfloat16 g_WT1H[DIM * DIM];
__device__ __align__(16) __nv_bfloat16 g_WT1L[DIM * DIM];
__device__ __align__(16) __nv_bfloat16 g_WT2H[DIM * DIM];
__device__ __align__(16) __nv_bfloat16 g_WT2L[DIM * DIM];
__device__ __align__(16) __nv_bfloat16 g_WTWH[DIM * DIM];
__device__ __align__(16) __nv_bfloat16 g_WTWL[DIM * DIM];

// ---------------- helpers ----------------
__device__ __forceinline__ uint32_t smem_u32(const void* p) {
    uint32_t a;
    asm("{ .reg .u64 t; cvta.to.shared.u64 t, %1; cvt.u32.u64 %0, t; }" : "=r"(a) : "l"(p));
    return a;
}
__device__ __forceinline__ void ldsm_x4(uint32_t addr, uint32_t* r) {
    asm volatile("ldmatrix.sync.aligned.m8n8.x4.shared.b16 {%0,%1,%2,%3}, [%4];"
                 : "=r"(r[0]), "=r"(r[1]), "=r"(r[2]), "=r"(r[3]) : "r"(addr));
}
__device__ __forceinline__ void mma_bf16(float* d, const uint32_t* a, uint32_t b0, uint32_t b1) {
    asm volatile(
        "mma.sync.aligned.m16n8k16.row.col.f32.bf16.bf16.f32 "
        "{%0,%1,%2,%3}, {%4,%5,%6,%7}, {%8,%9}, {%0,%1,%2,%3};"
        : "+f"(d[0]), "+f"(d[1]), "+f"(d[2]), "+f"(d[3])
        : "r"(a[0]), "r"(a[1]), "r"(a[2]), "r"(a[3]), "r"(b0), "r"(b1));
}
__device__ __forceinline__ void cp16(uint32_t saddr, const void* g) {
    asm volatile("cp.async.cg.shared.global [%0], [%1], 16;" :: "r"(saddr), "l"(g) : "memory");
}
__device__ __forceinline__ float sigmoidf(float x) {
    return 1.0f / (1.0f + __expf(-x));
}
__device__ __forceinline__ uint32_t pack_bf2(float a, float b) {
    __nv_bfloat162 t = __floats2bfloat162_rn(a, b);
    return *(uint32_t*)&t;
}
__device__ __forceinline__ void split4(float4 v, uint2& hi, uint2& lo) {
    float hx = __bfloat162float(__float2bfloat16_rn(v.x));
    float hy = __bfloat162float(__float2bfloat16_rn(v.y));
    float hz = __bfloat162float(__float2bfloat16_rn(v.z));
    float hw = __bfloat162float(__float2bfloat16_rn(v.w));
    hi.x = pack_bf2(hx, hy);  hi.y = pack_bf2(hz, hw);
    lo.x = pack_bf2(v.x - hx, v.y - hy);
    lo.y = pack_bf2(v.z - hz, v.w - hw);
}

// 3-term emulated bf16 MMA over a 128x128x128 tile, 16-warp version.
// Warp grid 4(m) x 4(n); warp tile 32x32. acc[2][4][4].
// Fragments loaded once per k-step: AH*BH + AH*BL + AL*BH.
__device__ __forceinline__ void mma_tile_3term16(
        uint32_t aHb, uint32_t aLb, uint32_t bHb, uint32_t bLb,
        int wm, int wn, int lrow, int lkh, float acc[2][4][4]) {
    #pragma unroll
    for (int ks = 0; ks < 8; ks++) {
        int kchunk = ks * 2 + lkh;
        uint32_t aH[2][4], aL[2][4], bH[2][4], bL[2][4];
        #pragma unroll
        for (int i = 0; i < 2; i++) {
            int row = wm * 32 + i * 16 + lrow;
            uint32_t o = row * 256 + ((kchunk ^ (row & 7)) << 4);
            ldsm_x4(aHb + o, aH[i]);
            ldsm_x4(aLb + o, aL[i]);
        }
        #pragma unroll
        for (int j2 = 0; j2 < 2; j2++) {
            int row = wn * 32 + j2 * 16 + lrow;
            uint32_t o = row * 256 + ((kchunk ^ (row & 7)) << 4);
            ldsm_x4(bHb + o, bH[j2]);
            ldsm_x4(bLb + o, bL[j2]);
        }
        #pragma unroll
        for (int i = 0; i < 2; i++)
            #pragma unroll
            for (int j = 0; j < 4; j++) {
                uint32_t h0 = bH[j >> 1][j & 1], h1 = bH[j >> 1][2 + (j & 1)];
                uint32_t l0 = bL[j >> 1][j & 1], l1 = bL[j >> 1][2 + (j & 1)];
                mma_bf16(acc[i][j], aH[i], h0, h1);
                mma_bf16(acc[i][j], aH[i], l0, l1);
                mma_bf16(acc[i][j], aL[i], h0, h1);
            }
    }
}

// ---------------- k_prep: edge histogram + weight transpose/split + g_bsum reset --------
__global__ void k_prep(const int* __restrict__ rows, int edge_blks,
                       const float* __restrict__ W1, const float* __restrict__ W2,
                       const float* __restrict__ W) {
    int tid = threadIdx.x;
    if ((int)blockIdx.x < edge_blks) {
        if (blockIdx.x == 0) g_bsum[tid] = 0;
        int gid = blockIdx.x * 256 + tid;
        if (gid < NEDGE) atomicAdd(&g_cnt[rows[gid]], 1);
    } else {
        int gid = (blockIdx.x - edge_blks) * 256 + tid;   // 0 .. 3*16384-1
        int m = gid >> 14, rem = gid & 16383, k = rem >> 7, n = rem & 127;
        const float* src = (m == 0) ? W1 : (m == 1) ? W2 : W;
        __nv_bfloat16* dh = (m == 0) ? g_WT1H : (m == 1) ? g_WT2H : g_WTWH;
        __nv_bfloat16* dl = (m == 0) ? g_WT1L : (m == 1) ? g_WT2L : g_WTWL;
        float v = src[k * DIM + n];
        __nv_bfloat16 h = __float2bfloat16_rn(v);
        dh[n * DIM + k] = h;
        dl[n * DIM + k] = __float2bfloat16_rn(v - __bfloat162float(h));
    }
}

// ---------------- single-launch scan (decoupled partials; all 196 blocks co-resident) ----
__global__ void k_scan_lb() {
    __shared__ int sh[256];
    __shared__ int red[256];
    int tid = threadIdx.x, b = blockIdx.x;
    int gid = b * 256 + tid;
    int v = (gid < N_ENT) ? g_cnt[gid] : 0;
    if (gid < N_ENT) g_cnt[gid] = 0;              // leave zeroed for next launch
    sh[tid] = v;
    __syncthreads();
    #pragma unroll
    for (int off = 1; off < 256; off <<= 1) {
        int t = 0;
        if (tid >= off) t = sh[tid - off];
        __syncthreads();
        sh[tid] += t;
        __syncthreads();
    }
    if (tid == 0) atomicExch(&g_bsum[b], sh[255] | READY_BIT);
    int myp = 0;
    if (tid < b) {
        int p;
        do { p = *(volatile int*)&g_bsum[tid]; } while (!(p & READY_BIT));
        myp = p & ~READY_BIT;
    }
    red[tid] = myp;
    __syncthreads();
    #pragma unroll
    for (int off = 128; off > 0; off >>= 1) {
        if (tid < off) red[tid] += red[tid + off];
        __syncthreads();
    }
    int prefix = red[0];
    if (gid < N_ENT) {
        int val = prefix + sh[tid] - v;
        g_rowptr[gid] = val;
        g_cur[gid] = val;
    }
    if (b == 0 && tid == 0) g_rowptr[N_ENT] = NEDGE;
}

__global__ void k_scatter(const int* __restrict__ rows, const int* __restrict__ cols,
                          const float* __restrict__ vals) {
    int gid = blockIdx.x * blockDim.x + threadIdx.x;
    if (gid < NEDGE) {
        int r = rows[gid];
        int pos = atomicAdd(&g_cur[r], 1);
        g_pedge[pos] = make_int2(cols[gid], __float_as_int(vals[gid]));
    }
}

// ---------------- HMMA GEMM, f32 gathered input (layer1 + wmat combined), 512 thr --------
#define LG_XH 0
#define LG_XL 32768
#define LG_WH 65536
#define LG_WL 98304
#define LG_SMEM 131072

__global__ void __launch_bounds__(512, 1) k_hgemm1c(
        const float* __restrict__ E, const float* __restrict__ R,
        const int* __restrict__ init_ind, const int* __restrict__ batch_rel,
        float* __restrict__ outA, float* __restrict__ outW) {
    extern __shared__ char sm[];
    int tid = threadIdx.x;

    const float* X;
    const __nv_bfloat16 *WTH, *WTL;
    const int* idx;
    float* out;
    int nrows, rbase;
    if ((int)blockIdx.x < N_TILES) {
        X = E;  WTH = g_WT1H; WTL = g_WT1L; idx = init_ind;  out = outA; nrows = N_ENT;
        rbase = blockIdx.x * 128;
    } else {
        X = R;  WTH = g_WTWH; WTL = g_WTWL; idx = batch_rel; out = outW; nrows = BATCH;
        rbase = (blockIdx.x - N_TILES) * 128;
    }

    const uint4* wh = (const uint4*)WTH;
    const uint4* wl = (const uint4*)WTL;
    #pragma unroll
    for (int l = tid; l < 2048; l += 512) {
        int r = l >> 4, c = l & 15;
        int off = r * 256 + ((c ^ (r & 7)) << 4);
        *(uint4*)(sm + LG_WH + off) = wh[l];
        *(uint4*)(sm + LG_WL + off) = wl[l];
    }
    #pragma unroll
    for (int l = tid; l < 2048; l += 512) {
        int r = l >> 4, c = l & 15;
        int gr = rbase + r;
        float4 v0 = make_float4(0.f, 0.f, 0.f, 0.f), v1 = v0;
        if (gr < nrows) {
            const float4* xp = (const float4*)X + (size_t)idx[gr] * 32 + c * 2;
            v0 = xp[0]; v1 = xp[1];
        }
        uint2 h0, l0, h1, l1;
        split4(v0, h0, l0); split4(v1, h1, l1);
        int off = r * 256 + ((c ^ (r & 7)) << 4);
        *(uint4*)(sm + LG_XH + off) = make_uint4(h0.x, h0.y, h1.x, h1.y);
        *(uint4*)(sm + LG_XL + off) = make_uint4(l0.x, l0.y, l1.x, l1.y);
    }
    __syncthreads();

    uint32_t smb = smem_u32(sm);
    int wid = tid >> 5, lane = tid & 31;
    int wm = wid >> 2, wn = wid & 3;
    int lrow = lane & 15, lkh = lane >> 4;

    float acc[2][4][4];
    #pragma unroll
    for (int i = 0; i < 2; i++)
        #pragma unroll
        for (int j = 0; j < 4; j++)
            #pragma unroll
            for (int f = 0; f < 4; f++) acc[i][j][f] = 0.f;

    mma_tile_3term16(smb + LG_XH, smb + LG_XL, smb + LG_WH, smb + LG_WL,
                     wm, wn, lrow, lkh, acc);

    int q = lane >> 2, p = lane & 3;
    #pragma unroll
    for (int i = 0; i < 2; i++) {
        int r0 = rbase + wm * 32 + i * 16 + q;
        #pragma unroll
        for (int j = 0; j < 4; j++) {
            int n = wn * 32 + j * 8 + p * 2;
            if (r0 < nrows)
                *(float2*)(out + (size_t)r0 * DIM + n) = make_float2(acc[i][j][0], acc[i][j][1]);
            if (r0 + 8 < nrows)
                *(float2*)(out + (size_t)(r0 + 8) * DIM + n) = make_float2(acc[i][j][2], acc[i][j][3]);
        }
    }
}

// ---------------- HMMA GEMM, pre-split bf16 input (layer 2), 512 thr ----------------
__global__ void __launch_bounds__(512, 1) k_hgemm2b(float* __restrict__ out) {
    extern __shared__ char sm[];
    uint32_t smb = smem_u32(sm);
    int tid = threadIdx.x;
    int rbase = blockIdx.x * 128;

    const uint4* xh = (const uint4*)g_h1H + (size_t)rbase * 16;
    const uint4* xl = (const uint4*)g_h1L + (size_t)rbase * 16;
    const uint4* wh = (const uint4*)g_WT2H;
    const uint4* wl = (const uint4*)g_WT2L;
    #pragma unroll
    for (int l = tid; l < 2048; l += 512) {
        int r = l >> 4, c = l & 15;
        uint32_t off = r * 256 + ((c ^ (r & 7)) << 4);
        cp16(smb + LG_XH + off, xh + l);
        cp16(smb + LG_XL + off, xl + l);
        cp16(smb + LG_WH + off, wh + l);
        cp16(smb + LG_WL + off, wl + l);
    }
    asm volatile("cp.async.commit_group;" ::: "memory");
    asm volatile("cp.async.wait_group 0;" ::: "memory");
    __syncthreads();

    int wid = tid >> 5, lane = tid & 31;
    int wm = wid >> 2, wn = wid & 3;
    int lrow = lane & 15, lkh = lane >> 4;

    float acc[2][4][4];
    #pragma unroll
    for (int i = 0; i < 2; i++)
        #pragma unroll
        for (int j = 0; j < 4; j++)
            #pragma unroll
            for (int f = 0; f < 4; f++) acc[i][j][f] = 0.f;

    mma_tile_3term16(smb + LG_XH, smb + LG_XL, smb + LG_WH, smb + LG_WL,
                     wm, wn, lrow, lkh, acc);

    int q = lane >> 2, p = lane & 3;
    #pragma unroll
    for (int i = 0; i < 2; i++) {
        int r0 = rbase + wm * 32 + i * 16 + q;
        #pragma unroll
        for (int j = 0; j < 4; j++) {
            int n = wn * 32 + j * 8 + p * 2;
            if (r0 < N_ENT)
                *(float2*)(out + (size_t)r0 * DIM + n) = make_float2(acc[i][j][0], acc[i][j][1]);
            if (r0 + 8 < N_ENT)
                *(float2*)(out + (size_t)(r0 + 8) * DIM + n) = make_float2(acc[i][j][2], acc[i][j][3]);
        }
    }
}

// ---------------- SpMM 1: h1 = split(relu(b1 + A @ src)) ----------------
__global__ void k_spmm1(const float* __restrict__ src, const float* __restrict__ bias) {
    int w = (blockIdx.x * blockDim.x + threadIdx.x) >> 5;
    int lane = threadIdx.x & 31;
    if (w >= N_ENT) return;
    int s = g_rowptr[w], e = g_rowptr[w + 1];
    const float4* s4 = (const float4*)src;
    float4 acc = ((const float4*)bias)[lane];
    for (int j = s; j < e; j++) {
        int2 pe = g_pedge[j];
        float v = __int_as_float(pe.y);
        float4 x = s4[(size_t)pe.x * 32 + lane];
        acc.x += v * x.x; acc.y += v * x.y; acc.z += v * x.z; acc.w += v * x.w;
    }
    acc.x = fmaxf(acc.x, 0.f); acc.y = fmaxf(acc.y, 0.f);
    acc.z = fmaxf(acc.z, 0.f); acc.w = fmaxf(acc.w, 0.f);
    uint2 hi, lo;
    split4(acc, hi, lo);
    ((uint2*)g_h1H)[w * 32 + lane] = hi;
    ((uint2*)g_h1L)[w * 32 + lane] = lo;
}

// ---------------- SpMM 2 fused: final = E[init] + relu(b2 + A @ src); + split ----------
__global__ void k_spmm2f(const float* __restrict__ src, const float* __restrict__ bias,
                         const float* __restrict__ E, const int* __restrict__ idx) {
    int w = (blockIdx.x * blockDim.x + threadIdx.x) >> 5;
    int lane = threadIdx.x & 31;
    if (w >= N_ENT) return;
    int s = g_rowptr[w], e = g_rowptr[w + 1];
    const float4* s4 = (const float4*)src;
    float4 acc = ((const float4*)bias)[lane];
    for (int j = s; j < e; j++) {
        int2 pe = g_pedge[j];
        float v = __int_as_float(pe.y);
        float4 x = s4[(size_t)pe.x * 32 + lane];
        acc.x += v * x.x; acc.y += v * x.y; acc.z += v * x.z; acc.w += v * x.w;
    }
    float4 e4 = ((const float4*)E)[(size_t)idx[w] * 32 + lane];
    e4.x += fmaxf(acc.x, 0.f); e4.y += fmaxf(acc.y, 0.f);
    e4.z += fmaxf(acc.z, 0.f); e4.w += fmaxf(acc.w, 0.f);
    ((float4*)g_final)[w * 32 + lane] = e4;
    uint2 hi, lo;
    split4(e4, hi, lo);
    ((uint2*)g_finalH)[w * 32 + lane] = hi;
    ((uint2*)g_finalL)[w * 32 + lane] = lo;
}

// ---------------- vm = bn1(bn0(final[bh]) * wmat); + split ----------------
__global__ void k_vm_split(const int* __restrict__ bh,
                           const float* __restrict__ g0, const float* __restrict__ b0,
                           const float* __restrict__ g1, const float* __restrict__ b1) {
    int gid = blockIdx.x * blockDim.x + threadIdx.x;
    if (gid >= BATCH * 32) return;
    int b = gid >> 5, qq = gid & 31;
    float s = rsqrtf(1.0f + BN_EPS);
    float4 G0 = ((const float4*)g0)[qq], B0 = ((const float4*)b0)[qq];
    float4 G1 = ((const float4*)g1)[qq], B1 = ((const float4*)b1)[qq];
    float4 x = ((const float4*)g_final)[(size_t)bh[b] * 32 + qq];
    float4 wm = ((const float4*)g_wmat)[gid];
    float4 r;
    r.x = ((x.x * (G0.x * s) + B0.x) * wm.x) * (G1.x * s) + B1.x;
    r.y = ((x.y * (G0.y * s) + B0.y) * wm.y) * (G1.y * s) + B1.y;
    r.z = ((x.z * (G0.z * s) + B0.z) * wm.z) * (G1.z * s) + B1.z;
    r.w = ((x.w * (G0.w * s) + B0.w) * wm.w) * (G1.w * s) + B1.w;
    uint2 hi, lo;
    split4(r, hi, lo);
    ((uint2*)g_vmH)[gid] = hi;
    ((uint2*)g_vmL)[gid] = lo;
}

// ---------------- persistent double-buffered big GEMM, 512 thr --------------------------
#define PG_AH 0
#define PG_AL 32768
#define PG_B0 65536
#define PG_B1 131072
#define PG_SMEM 196608

__global__ void __launch_bounds__(512, 1) k_biggemm_persist(float* __restrict__ out) {
    extern __shared__ char sm[];
    uint32_t smb = smem_u32(sm);
    int tid = threadIdx.x;
    int cta = blockIdx.x;

    // balanced contiguous chunks: 3128 = 20*22 + 128*21
    int start, cnt;
    if (cta < 20) { start = cta * 22; cnt = 22; }
    else          { start = 440 + (cta - 20) * 21; cnt = 21; }
    int end = start + cnt;

    const uint4* Ah = (const uint4*)g_vmH;
    const uint4* Al = (const uint4*)g_vmL;
    const uint4* Bh = (const uint4*)g_finalH;
    const uint4* Bl = (const uint4*)g_finalL;

    int wid = tid >> 5, lane = tid & 31;
    int wm = wid >> 2, wn = wid & 3;
    int lrow = lane & 15, lkh = lane >> 4;
    int q = lane >> 2, p = lane & 3;

    int cur_b = -1, buf = 0, loaded = 0;

    for (int t = start; t < end; t++) {
        int b = t / N_TILES, n = t - b * N_TILES;
        __syncthreads();

        if (!loaded) {
            if (b != cur_b) {
                int bbase = b * 128;
                #pragma unroll
                for (int l = tid; l < 2048; l += 512) {
                    int r = l >> 4, c = l & 15;
                    uint32_t off = r * 256 + ((c ^ (r & 7)) << 4);
                    cp16(smb + PG_AH + off, Ah + (size_t)(bbase + r) * 16 + c);
                    cp16(smb + PG_AL + off, Al + (size_t)(bbase + r) * 16 + c);
                }
                cur_b = b;
            }
            int nbase = n * 128;
            uint32_t sb = smb + (buf ? PG_B1 : PG_B0);
            #pragma unroll
            for (int l = tid; l < 2048; l += 512) {
                int r = l >> 4, c = l & 15;
                uint32_t off = r * 256 + ((c ^ (r & 7)) << 4);
                cp16(sb + off,         Bh + (size_t)(nbase + r) * 16 + c);
                cp16(sb + 32768 + off, Bl + (size_t)(nbase + r) * 16 + c);
            }
            asm volatile("cp.async.commit_group;" ::: "memory");
        }

        int pf = 0;
        if (t + 1 < end) {
            int b2 = (t + 1) / N_TILES, n2 = (t + 1) - b2 * N_TILES;
            if (b2 == cur_b) {
                int nbase2 = n2 * 128;
                uint32_t sb2 = smb + (buf ? PG_B0 : PG_B1);
                #pragma unroll
                for (int l = tid; l < 2048; l += 512) {
                    int r = l >> 4, c = l & 15;
                    uint32_t off = r * 256 + ((c ^ (r & 7)) << 4);
                    cp16(sb2 + off,         Bh + (size_t)(nbase2 + r) * 16 + c);
                    cp16(sb2 + 32768 + off, Bl + (size_t)(nbase2 + r) * 16 + c);
                }
                asm volatile("cp.async.commit_group;" ::: "memory");
                pf = 1;
            }
        }
        if (pf) asm volatile("cp.async.wait_group 1;" ::: "memory");
        else    asm volatile("cp.async.wait_group 0;" ::: "memory");
        __syncthreads();

        uint32_t sb = smb + (buf ? PG_B1 : PG_B0);
        float acc[2][4][4];
        #pragma unroll
        for (int i = 0; i < 2; i++)
            #pragma unroll
            for (int j = 0; j < 4; j++)
                #pragma unroll
                for (int f = 0; f < 4; f++) acc[i][j][f] = 0.f;

        mma_tile_3term16(smb + PG_AH, smb + PG_AL, sb, sb + 32768,
                         wm, wn, lrow, lkh, acc);

        int bbase = b * 128, nbase = n * 128;
        #pragma unroll
        for (int i = 0; i < 2; i++) {
            int brow = bbase + wm * 32 + i * 16 + q;
            #pragma unroll
            for (int j = 0; j < 4; j++) {
                int nn = nbase + wn * 32 + j * 8 + p * 2;
                if (nn < N_ENT) {
                    float2 o0, o1;
                    o0.x = sigmoidf(acc[i][j][0]); o0.y = sigmoidf(acc[i][j][1]);
                    o1.x = sigmoidf(acc[i][j][2]); o1.y = sigmoidf(acc[i][j][3]);
                    *(float2*)(out + (size_t)brow * N_ENT + nn) = o0;
                    *(float2*)(out + (size_t)(brow + 8) * N_ENT + nn) = o1;
                }
            }
        }

        loaded = pf;
        buf ^= 1;
    }
}

// ---------------- orchestration ----------------
extern "C" void kernel_launch(void* const* d_in, const int* in_sizes, int n_in,
                              void* d_out, int out_size) {
    const float* E_emb     = (const float*)d_in[0];
    const float* R_emb     = (const float*)d_in[1];
    const float* W1        = (const float*)d_in[2];
    const float* b1        = (const float*)d_in[3];
    const float* W2        = (const float*)d_in[4];
    const float* b2        = (const float*)d_in[5];
    const float* W         = (const float*)d_in[6];
    const float* adj_vals  = (const float*)d_in[7];
    const float* bn0_gamma = (const float*)d_in[8];
    const float* bn0_beta  = (const float*)d_in[9];
    const float* bn1_gamma = (const float*)d_in[10];
    const float* bn1_beta  = (const float*)d_in[11];
    const int*   batch_head = (const int*)d_in[12];
    const int*   batch_rel  = (const int*)d_in[13];
    const int*   init_ind   = (const int*)d_in[14];
    const int*   adj_rows   = (const int*)d_in[15];
    const int*   adj_cols   = (const int*)d_in[16];
    float* out = (float*)d_out;

    float *pA, *pWM;
    cudaGetSymbolAddress((void**)&pA, g_bufA);
    cudaGetSymbolAddress((void**)&pWM, g_wmat);

    cudaFuncSetAttribute(k_hgemm1c, cudaFuncAttributeMaxDynamicSharedMemorySize, LG_SMEM);
    cudaFuncSetAttribute(k_hgemm2b, cudaFuncAttributeMaxDynamicSharedMemorySize, LG_SMEM);
    cudaFuncSetAttribute(k_biggemm_persist, cudaFuncAttributeMaxDynamicSharedMemorySize, PG_SMEM);

    const int EDGE_BLKS = (NEDGE + 255) / 256;          // 3125
    const int ENT_BLKS  = (N_ENT + 255) / 256;          // 196
    const int ROWW_BLKS = (N_ENT * 32 + 255) / 256;     // 6250

    // 1. histogram + weight splits (+ g_bsum reset)
    k_prep<<<EDGE_BLKS + 192, 256>>>(adj_rows, EDGE_BLKS, W1, W2, W);
    // 2. single-launch scan (also zeroes g_cnt for next launch)
    k_scan_lb<<<ENT_BLKS, 256>>>();
    // 3. CSR scatter
    k_scatter<<<EDGE_BLKS, 256>>>(adj_rows, adj_cols, adj_vals);
    // 4. layer-1 GEMM + wmat GEMM (combined launch)
    k_hgemm1c<<<N_TILES + BATCH / 128, 512, LG_SMEM>>>(E_emb, R_emb, init_ind, batch_rel, pA, pWM);
    // 5. SpMM1 (+relu+split)
    k_spmm1<<<ROWW_BLKS, 256>>>(pA, b1);
    // 6. layer-2 GEMM (bf16 in, f32 out)
    k_hgemm2b<<<N_TILES, 512, LG_SMEM>>>(pA);
    // 7. SpMM2 (+residual+relu+split)
    k_spmm2f<<<ROWW_BLKS, 256>>>(pA, b2, E_emb, init_ind);
    // 8. vm (+split)
    k_vm_split<<<(BATCH * 32 + 255) / 256, 256>>>(batch_head, bn0_gamma, bn0_beta, bn1_gamma, bn1_beta);
    // 9. persistent tensor-core scoring GEMM + sigmoid
    k_biggemm_persist<<<148, 512, PG_SMEM>>>(out);
}